// round 1
// baseline (speedup 1.0000x reference)
#include <cuda_runtime.h>
#include <cstdint>
#include <math.h>

#define Bn   16
#define Ln   5000
#define Hn   256
#define Nn   32
#define NLn  4
#define DINn 12

// ---------------- scratch (device globals; no runtime allocation) ----------------
__device__ float  d_X [(size_t)Bn * Ln * Hn];   // activations (B, L, H)
__device__ float  d_Zt[(size_t)Bn * Hn * Ln];   // LN output, transposed (B, H, L)
__device__ float  d_Gt[(size_t)Bn * Hn * Ln];   // gelu(conv+skip), transposed (B, H, L)
__device__ float4 d_SSMP[NLn * Hn * Nn];        // (lam_re, lam_im, 2*Ct_re, 2*Ct_im)
__device__ float  d_W2[NLn * Hn * 2 * Hn];      // W_glu with interleaved halves
__device__ float  d_b2[NLn * 2 * Hn];           // b_glu interleaved

// ---------------- helpers ----------------
__device__ __forceinline__ float to_tf32(float x) {
    uint32_t u;
    asm("cvt.rna.tf32.f32 %0, %1;" : "=r"(u) : "f"(x));
    return __uint_as_float(u);
}

__device__ __forceinline__ void mma_tf32(float* d, const uint32_t* a, const uint32_t* b) {
    asm volatile(
        "mma.sync.aligned.m16n8k8.row.col.f32.tf32.tf32.f32 "
        "{%0,%1,%2,%3}, {%4,%5,%6,%7}, {%8,%9}, {%0,%1,%2,%3};\n"
        : "+f"(d[0]), "+f"(d[1]), "+f"(d[2]), "+f"(d[3])
        : "r"(a[0]), "r"(a[1]), "r"(a[2]), "r"(a[3]), "r"(b[0]), "r"(b[1]));
}

__device__ __forceinline__ float gelu_tanh(float x) {
    float x3 = x * x * x;
    return 0.5f * x * (1.f + tanhf(0.7978845608028654f * fmaf(0.044715f, x3, x)));
}

// ---------------- param prep ----------------
__global__ __launch_bounds__(256) void prep_ssm(
    const float* __restrict__ log_dt, const float* __restrict__ logA_re,
    const float* __restrict__ A_im,   const float* __restrict__ Cp)
{
    int idx = blockIdx.x * 256 + threadIdx.x;      // NL*H*N = 32768
    int i = idx / (Hn * Nn);
    int h = (idx / Nn) % Hn;
    float dt  = expf(log_dt[i * Hn + h]);
    float aRe = -expf(logA_re[idx]);
    float aIm = A_im[idx];
    float er  = expf(aRe * dt);
    float ang = aIm * dt;
    float lr = er * cosf(ang), li = er * sinf(ang);
    // (lam - 1) / A
    float nr = lr - 1.f, ni = li;
    float inv = 1.f / (aRe * aRe + aIm * aIm);
    float qr = (nr * aRe + ni * aIm) * inv;
    float qi = (ni * aRe - nr * aIm) * inv;
    float cr = Cp[2 * idx], ci = Cp[2 * idx + 1];
    float Ctr = cr * qr - ci * qi;
    float Cti = cr * qi + ci * qr;
    d_SSMP[idx] = make_float4(lr, li, 2.f * Ctr, 2.f * Cti);
}

__global__ __launch_bounds__(256) void prep_w2(
    const float* __restrict__ W_glu, const float* __restrict__ b_glu)
{
    int idx = blockIdx.x * 256 + threadIdx.x;      // NL*H*256 = 262144
    int i = idx >> 16;
    int rem = idx & 65535;
    int h = rem >> 8;
    int j = rem & 255;
    const float* src = W_glu + ((size_t)i * Hn + h) * (2 * Hn);
    float* dst = d_W2 + ((size_t)i * Hn + h) * (2 * Hn);
    dst[2 * j]     = src[j];
    dst[2 * j + 1] = src[j + Hn];
    if (idx < NLn * Hn) {       // 1024 threads fill b2
        int i2 = idx >> 8, j2 = idx & 255;
        d_b2[i2 * 512 + 2 * j2]     = b_glu[i2 * 512 + j2];
        d_b2[i2 * 512 + 2 * j2 + 1] = b_glu[i2 * 512 + Hn + j2];
    }
}

// ---------------- input projection: X = x @ W_in + b_in ----------------
__global__ __launch_bounds__(256) void in_proj(
    const float* __restrict__ x, const float* __restrict__ W, const float* __restrict__ bias)
{
    __shared__ float xs[32][DINn];
    int tid = threadIdx.x;
    int r0 = blockIdx.x * 32;                        // 2500 blocks * 32 rows = 80000
    for (int t = tid; t < 32 * DINn; t += 256)
        xs[t / DINn][t % DINn] = x[(size_t)r0 * DINn + t];
    float w[DINn];
#pragma unroll
    for (int k = 0; k < DINn; k++) w[k] = W[k * Hn + tid];
    float bv = bias[tid];
    __syncthreads();
#pragma unroll 4
    for (int r = 0; r < 32; r++) {
        float a = bv;
#pragma unroll
        for (int k = 0; k < DINn; k++) a = fmaf(xs[r][k], w[k], a);
        d_X[((size_t)(r0 + r)) * Hn + tid] = a;
    }
}

// ---------------- LayerNorm + transpose to (B, H, L) ----------------
__global__ __launch_bounds__(256) void ln_t_kernel(
    int layer, const float* __restrict__ ln_g, const float* __restrict__ ln_b)
{
    __shared__ float tile[32][257];
    __shared__ float mu[32], sc[32];
    int b  = blockIdx.y;
    int l0 = blockIdx.x * 32;
    int tid = threadIdx.x, lane = tid & 31, wid = tid >> 5;
    const float* Xb = d_X + (size_t)b * Ln * Hn;
#pragma unroll
    for (int r = 0; r < 32; r++) {
        int l = l0 + r;
        tile[r][tid] = (l < Ln) ? Xb[(size_t)l * Hn + tid] : 0.f;
    }
    __syncthreads();
#pragma unroll
    for (int rr = 0; rr < 4; rr++) {
        int r = wid * 4 + rr;
        float s = 0.f, q = 0.f;
#pragma unroll
        for (int k = 0; k < 8; k++) {
            float v = tile[r][k * 32 + lane];
            s += v; q += v * v;
        }
#pragma unroll
        for (int o = 16; o; o >>= 1) {
            s += __shfl_xor_sync(0xffffffffu, s, o);
            q += __shfl_xor_sync(0xffffffffu, q, o);
        }
        if (lane == 0) {
            float m = s * (1.f / 256.f);
            float v = q * (1.f / 256.f) - m * m;
            mu[r] = m;
            sc[r] = rsqrtf(v + 1e-5f);
        }
    }
    __syncthreads();
    const float* g  = ln_g + layer * Hn;
    const float* bb = ln_b + layer * Hn;
    float* Zb = d_Zt + (size_t)b * Hn * Ln;
    int l = l0 + lane;
    if (l < Ln) {
        float m = mu[lane], s = sc[lane];
#pragma unroll
        for (int hi = 0; hi < 32; hi++) {
            int h = wid * 32 + hi;
            Zb[(size_t)h * Ln + l] = (tile[lane][h] - m) * s * g[h] + bb[h];
        }
    }
}

// ---------------- SSM scan: Gt = gelu(conv(K,z) + D*z), warp per (b,h), lane per mode ---
__global__ __launch_bounds__(256) void scan_kernel(int layer, const float* __restrict__ Dp)
{
    __shared__ float red[8][32][33];
    int lane = threadIdx.x & 31, wid = threadIdx.x >> 5;
    int w = blockIdx.x * 8 + wid;           // 0..4095
    int b = w >> 8, h = w & 255;
    float4 p = d_SSMP[(layer * Hn + h) * Nn + lane];
    float lr = p.x, li = p.y, ctr = p.z, cti = p.w;
    float Dh = Dp[layer * Hn + h];
    const float* u = d_Zt + (size_t)(b * Hn + h) * Ln;
    float* gOut = d_Gt + (size_t)(b * Hn + h) * Ln;
    float pr = 0.f, pi = 0.f;
    for (int c0 = 0; c0 < Ln; c0 += 32) {
        int l = c0 + lane;
        float uv = (l < Ln) ? u[l] : 0.f;
#pragma unroll
        for (int s = 0; s < 32; s++) {
            float us  = __shfl_sync(0xffffffffu, uv, s);
            float t1  = fmaf(-li, pi, ctr * us);
            float t2  = fmaf( lr, pi, cti * us);
            float prn = fmaf( lr, pr, t1);
            pi        = fmaf( li, pr, t2);
            pr = prn;
            red[wid][lane][s] = pr;
        }
        __syncwarp();
        float acc = 0.f;
#pragma unroll
        for (int n = 0; n < 32; n++) acc += red[wid][n][lane];
        __syncwarp();
        if (l < Ln) {
            float y = fmaf(Dh, uv, acc);
            gOut[l] = gelu_tanh(y);
        }
    }
}

// ---------------- GLU GEMM (tf32 mma) + bias + GLU + residual ----------------
// C[M=l, N=512] = Gt[b]^T (M x K=256) @ W2 (K x 512); GLU pairs are adjacent cols.
__global__ __launch_bounds__(256) void glu_gemm_kernel(int layer)
{
    const int m0 = blockIdx.x * 128;     // 40 tiles over L
    const int n0 = blockIdx.y * 128;     // 4 tiles over 512
    const int b  = blockIdx.z;
    __shared__ float As[32][132];
    __shared__ float Bs[32][132];
    int tid = threadIdx.x;
    int lane = tid & 31, wid = tid >> 5;
    int wm = wid & 3, wn = wid >> 2;     // 4 x 2 warp grid; warp tile 32(M) x 64(N)
    float acc[2][8][4];
#pragma unroll
    for (int a = 0; a < 2; a++)
#pragma unroll
        for (int c = 0; c < 8; c++)
#pragma unroll
            for (int d = 0; d < 4; d++) acc[a][c][d] = 0.f;

    const float* Ag = d_Gt + (size_t)b * (Hn * Ln);
    const float* Bg = d_W2 + (size_t)layer * (Hn * 2 * Hn);
    int tg = lane & 3, gp = lane >> 2;

    for (int kt = 0; kt < Hn; kt += 32) {
#pragma unroll
        for (int i = 0; i < 16; i++) {
            int idx = tid + i * 256;
            int k = idx >> 7, m = idx & 127;
            int gl = m0 + m;
            float v = (gl < Ln) ? Ag[(size_t)(kt + k) * Ln + gl] : 0.f;
            As[k][m] = to_tf32(v);
        }
#pragma unroll
        for (int i = 0; i < 16; i++) {
            int idx = tid + i * 256;
            int k = idx >> 7, n = idx & 127;
            Bs[k][n] = to_tf32(Bg[(kt + k) * 512 + n0 + n]);
        }
        __syncthreads();
#pragma unroll
        for (int ks = 0; ks < 32; ks += 8) {
            uint32_t af[2][4], bf[8][2];
#pragma unroll
            for (int mi = 0; mi < 2; mi++) {
                int mb = wm * 32 + mi * 16;
                af[mi][0] = __float_as_uint(As[ks + tg    ][mb + gp    ]);
                af[mi][1] = __float_as_uint(As[ks + tg    ][mb + gp + 8]);
                af[mi][2] = __float_as_uint(As[ks + tg + 4][mb + gp    ]);
                af[mi][3] = __float_as_uint(As[ks + tg + 4][mb + gp + 8]);
            }
#pragma unroll
            for (int ni = 0; ni < 8; ni++) {
                int nb = wn * 64 + ni * 8;
                bf[ni][0] = __float_as_uint(Bs[ks + tg    ][nb + gp]);
                bf[ni][1] = __float_as_uint(Bs[ks + tg + 4][nb + gp]);
            }
#pragma unroll
            for (int mi = 0; mi < 2; mi++)
#pragma unroll
                for (int ni = 0; ni < 8; ni++)
                    mma_tf32(acc[mi][ni], af[mi], bf[ni]);
        }
        __syncthreads();
    }

    // epilogue: bias + GLU (even=a, odd=gate) + residual(Zt) -> X (B,L,H)
    const float* Zb  = d_Zt + (size_t)b * (Hn * Ln);
    const float* b2p = d_b2 + layer * 512;
#pragma unroll
    for (int mi = 0; mi < 2; mi++) {
        int mrow = wm * 32 + mi * 16 + gp;
#pragma unroll
        for (int ni = 0; ni < 8; ni++) {
            int nc = wn * 64 + ni * 8 + tg * 2;       // even col in tile
            int j  = (n0 + nc) >> 1;                  // output channel
            float ba = b2p[n0 + nc], bb = b2p[n0 + nc + 1];
#pragma unroll
            for (int hf = 0; hf < 2; hf++) {
                int l = m0 + mrow + hf * 8;
                if (l < Ln) {
                    float a    = acc[mi][ni][hf * 2 + 0] + ba;
                    float gate = acc[mi][ni][hf * 2 + 1] + bb;
                    float o = a * (1.f / (1.f + expf(-gate)));
                    o += Zb[(size_t)j * Ln + l];
                    d_X[((size_t)b * Ln + l) * Hn + j] = o;
                }
            }
        }
    }
}

// ---------------- final LayerNorm -> d_out (B, L, H) ----------------
__global__ __launch_bounds__(256) void final_ln(
    const float* __restrict__ g, const float* __restrict__ bb, float* __restrict__ out)
{
    int lane = threadIdx.x & 31, wid = threadIdx.x >> 5;
    size_t row = (size_t)blockIdx.x * 8 + wid;     // 80000 rows exactly
    const float* xr = d_X + row * Hn;
    float v[8], s = 0.f, q = 0.f;
#pragma unroll
    for (int k = 0; k < 8; k++) {
        v[k] = xr[k * 32 + lane];
        s += v[k]; q += v[k] * v[k];
    }
#pragma unroll
    for (int o = 16; o; o >>= 1) {
        s += __shfl_xor_sync(0xffffffffu, s, o);
        q += __shfl_xor_sync(0xffffffffu, q, o);
    }
    float m  = s * (1.f / 256.f);
    float sc = rsqrtf(q * (1.f / 256.f) - m * m + 1e-5f);
#pragma unroll
    for (int k = 0; k < 8; k++) {
        int h = k * 32 + lane;
        out[row * Hn + h] = (v[k] - m) * sc * g[h] + bb[h];
    }
}

// ---------------- launch ----------------
extern "C" void kernel_launch(void* const* d_in, const int* in_sizes, int n_in,
                              void* d_out, int out_size)
{
    const float* x       = (const float*)d_in[0];
    const float* W_in    = (const float*)d_in[1];
    const float* b_in    = (const float*)d_in[2];
    const float* ln_g    = (const float*)d_in[3];
    const float* ln_b    = (const float*)d_in[4];
    const float* log_dt  = (const float*)d_in[5];
    const float* logA_re = (const float*)d_in[6];
    const float* A_im    = (const float*)d_in[7];
    const float* Cp      = (const float*)d_in[8];
    const float* Dp      = (const float*)d_in[9];
    const float* W_glu   = (const float*)d_in[10];
    const float* b_glu   = (const float*)d_in[11];
    const float* fn_g    = (const float*)d_in[12];
    const float* fn_b    = (const float*)d_in[13];
    float* out = (float*)d_out;

    prep_ssm<<<128, 256>>>(log_dt, logA_re, A_im, Cp);
    prep_w2<<<1024, 256>>>(W_glu, b_glu);
    in_proj<<<2500, 256>>>(x, W_in, b_in);

    for (int i = 0; i < NLn; i++) {
        dim3 gln((Ln + 31) / 32, Bn);                 // 157 x 16
        ln_t_kernel<<<gln, 256>>>(i, ln_g, ln_b);
        scan_kernel<<<(Bn * Hn) / 8, 256>>>(i, Dp);   // 512 blocks
        dim3 gg((Ln + 127) / 128, 4, Bn);             // 40 x 4 x 16
        glu_gemm_kernel<<<gg, 256>>>(i);
    }
    final_ln<<<(Bn * Ln) / 8, 256>>>(fn_g, fn_b, out);
}

// round 2
// speedup vs baseline: 1.1911x; 1.1911x over previous
#include <cuda_runtime.h>
#include <cstdint>
#include <math.h>

#define Bn   16
#define Ln   5000
#define Hn   256
#define Nn   32
#define NLn  4
#define DINn 12
#define Tc   128          // chunk length
#define Cc   40           // chunks (padded length 5120)
#define LP   5120         // padded L

// ---------------- scratch (device globals; zero-initialized) ----------------
__device__ float  d_X [(size_t)Bn * Ln * Hn];    // activations (B, L, H)
__device__ float  d_Zt[(size_t)Bn * Hn * LP];    // LN output, (B, H, Lpad); pad stays 0
__device__ float  d_Gt[(size_t)Bn * Hn * LP];    // gelu(conv+skip), (B, H, Lpad)
__device__ float4 d_SSMP[NLn * Hn * Nn];         // (lam_re, lam_im, 2*Ct_re, 2*Ct_im)
__device__ float  d_W2[NLn * Hn * 2 * Hn];       // W_glu interleaved halves
__device__ float  d_b2[NLn * 2 * Hn];
__device__ float  d_Q [(size_t)Bn * Hn * Cc * 64];   // chunk state contributions
__device__ float  d_P [(size_t)Bn * Hn * Cc * 64];   // chunk-start states
__device__ float  d_W1[(size_t)NLn * Hn * Tc * 64];  // stage-1 B matrix
__device__ float  d_B3[(size_t)NLn * Hn * 192 * Tc]; // stage-3 B matrix (Toeplitz+D | V)
__device__ float  d_Kv[NLn * Hn * Tc];               // kernel K[h, 0..127]
__device__ float2 d_lamT[NLn * Hn * Nn];             // lambda^128

// ---------------- helpers ----------------
__device__ __forceinline__ float to_tf32(float x) {
    uint32_t u;
    asm("cvt.rna.tf32.f32 %0, %1;" : "=r"(u) : "f"(x));
    return __uint_as_float(u);
}

__device__ __forceinline__ void mma_tf32(float* d, const uint32_t* a, const uint32_t* b) {
    asm volatile(
        "mma.sync.aligned.m16n8k8.row.col.f32.tf32.tf32.f32 "
        "{%0,%1,%2,%3}, {%4,%5,%6,%7}, {%8,%9}, {%0,%1,%2,%3};\n"
        : "+f"(d[0]), "+f"(d[1]), "+f"(d[2]), "+f"(d[3])
        : "r"(a[0]), "r"(a[1]), "r"(a[2]), "r"(a[3]), "r"(b[0]), "r"(b[1]));
}

__device__ __forceinline__ float gelu_tanh(float x) {
    float x3 = x * x * x;
    return 0.5f * x * (1.f + tanhf(0.7978845608028654f * fmaf(0.044715f, x3, x)));
}

// ---------------- param prep ----------------
__global__ __launch_bounds__(256) void prep_ssm(
    const float* __restrict__ log_dt, const float* __restrict__ logA_re,
    const float* __restrict__ A_im,   const float* __restrict__ Cp)
{
    int idx = blockIdx.x * 256 + threadIdx.x;      // NL*H*N = 32768
    int i = idx / (Hn * Nn);
    int h = (idx / Nn) % Hn;
    float dt  = expf(log_dt[i * Hn + h]);
    float aRe = -expf(logA_re[idx]);
    float aIm = A_im[idx];
    float er  = expf(aRe * dt);
    float ang = aIm * dt;
    float lr = er * cosf(ang), li = er * sinf(ang);
    float nr = lr - 1.f, ni = li;
    float inv = 1.f / (aRe * aRe + aIm * aIm);
    float qr = (nr * aRe + ni * aIm) * inv;
    float qi = (ni * aRe - nr * aIm) * inv;
    float cr = Cp[2 * idx], ci = Cp[2 * idx + 1];
    float Ctr = cr * qr - ci * qi;
    float Cti = cr * qi + ci * qr;
    d_SSMP[idx] = make_float4(lr, li, 2.f * Ctr, 2.f * Cti);
}

// powers of lambda -> W1 (stage1 B), V rows of B3, lamT, K vector
__global__ __launch_bounds__(256) void prep_pow()
{
    int gw = blockIdx.x * 8 + (threadIdx.x >> 5);   // 0..1023 = layer*256+h
    int n  = threadIdx.x & 31;
    float4 p = d_SSMP[gw * 32 + n];
    float lr = p.x, li = p.y, tcr = p.z, tci = p.w;  // (lambda, 2*Ct)
    float curr = 1.f, curi = 0.f;                    // lambda^j
    float* W1p = d_W1 + (size_t)gw * (Tc * 64);
    float* B3p = d_B3 + (size_t)gw * (192 * Tc);
    float* Kvp = d_Kv + gw * Tc;
    for (int j = 0; j <= 128; j++) {
        if (j < 128) {
            float kr = tcr * curr - tci * curi;
            float ki = tcr * curi + tci * curr;
            W1p[(127 - j) * 64 + n]      = to_tf32(kr);
            W1p[(127 - j) * 64 + 32 + n] = to_tf32(ki);
            float s = kr;
#pragma unroll
            for (int o = 16; o; o >>= 1) s += __shfl_xor_sync(0xffffffffu, s, o);
            if (n == 0) Kvp[j] = s;
        }
        if (j >= 1) {
            int i = j - 1;
            B3p[(128 + n) * Tc + i] = to_tf32(curr);    //  Re(lambda^{i+1})
            B3p[(160 + n) * Tc + i] = to_tf32(-curi);   // -Im(lambda^{i+1})
        }
        if (j == 128) d_lamT[gw * 32 + n] = make_float2(curr, curi);
        float nr2 = curr * lr - curi * li;
        curi = curr * li + curi * lr;
        curr = nr2;
    }
}

// Toeplitz rows of B3 (with D folded into the diagonal)
__global__ __launch_bounds__(128) void prep_tk(const float* __restrict__ Dp)
{
    int gw = blockIdx.x;          // layer*256+h
    int i  = threadIdx.x;         // 0..127
    __shared__ float Ks[Tc];
    Ks[i] = d_Kv[gw * Tc + i];
    __syncthreads();
    float Dh = Dp[gw];
    float* B3p = d_B3 + (size_t)gw * (192 * Tc);
    for (int j = 0; j < 128; j++) {
        float v = 0.f;
        if (i >= j) v = Ks[i - j] + (i == j ? Dh : 0.f);
        B3p[j * Tc + i] = to_tf32(v);
    }
}

__global__ __launch_bounds__(256) void prep_w2(
    const float* __restrict__ W_glu, const float* __restrict__ b_glu)
{
    int idx = blockIdx.x * 256 + threadIdx.x;      // NL*H*256 = 262144
    int i = idx >> 16;
    int rem = idx & 65535;
    int h = rem >> 8;
    int j = rem & 255;
    const float* src = W_glu + ((size_t)i * Hn + h) * (2 * Hn);
    float* dst = d_W2 + ((size_t)i * Hn + h) * (2 * Hn);
    dst[2 * j]     = src[j];
    dst[2 * j + 1] = src[j + Hn];
    if (idx < NLn * Hn) {
        int i2 = idx >> 8, j2 = idx & 255;
        d_b2[i2 * 512 + 2 * j2]     = b_glu[i2 * 512 + j2];
        d_b2[i2 * 512 + 2 * j2 + 1] = b_glu[i2 * 512 + Hn + j2];
    }
}

// ---------------- input projection ----------------
__global__ __launch_bounds__(256) void in_proj(
    const float* __restrict__ x, const float* __restrict__ W, const float* __restrict__ bias)
{
    __shared__ float xs[32][DINn];
    int tid = threadIdx.x;
    int r0 = blockIdx.x * 32;
    for (int t = tid; t < 32 * DINn; t += 256)
        xs[t / DINn][t % DINn] = x[(size_t)r0 * DINn + t];
    float w[DINn];
#pragma unroll
    for (int k = 0; k < DINn; k++) w[k] = W[k * Hn + tid];
    float bv = bias[tid];
    __syncthreads();
#pragma unroll 4
    for (int r = 0; r < 32; r++) {
        float a = bv;
#pragma unroll
        for (int k = 0; k < DINn; k++) a = fmaf(xs[r][k], w[k], a);
        d_X[((size_t)(r0 + r)) * Hn + tid] = a;
    }
}

// ---------------- LayerNorm + transpose to (B, H, Lpad) ----------------
__global__ __launch_bounds__(256) void ln_t_kernel(
    int layer, const float* __restrict__ ln_g, const float* __restrict__ ln_b)
{
    __shared__ float tile[32][257];
    __shared__ float mu[32], sc[32];
    int b  = blockIdx.y;
    int l0 = blockIdx.x * 32;
    int tid = threadIdx.x, lane = tid & 31, wid = tid >> 5;
    const float* Xb = d_X + (size_t)b * Ln * Hn;
#pragma unroll
    for (int r = 0; r < 32; r++) {
        int l = l0 + r;
        tile[r][tid] = (l < Ln) ? Xb[(size_t)l * Hn + tid] : 0.f;
    }
    __syncthreads();
#pragma unroll
    for (int rr = 0; rr < 4; rr++) {
        int r = wid * 4 + rr;
        float s = 0.f, q = 0.f;
#pragma unroll
        for (int k = 0; k < 8; k++) {
            float v = tile[r][k * 32 + lane];
            s += v; q += v * v;
        }
#pragma unroll
        for (int o = 16; o; o >>= 1) {
            s += __shfl_xor_sync(0xffffffffu, s, o);
            q += __shfl_xor_sync(0xffffffffu, q, o);
        }
        if (lane == 0) {
            float m = s * (1.f / 256.f);
            float v = q * (1.f / 256.f) - m * m;
            mu[r] = m;
            sc[r] = rsqrtf(v + 1e-5f);
        }
    }
    __syncthreads();
    const float* g  = ln_g + layer * Hn;
    const float* bb = ln_b + layer * Hn;
    float* Zb = d_Zt + (size_t)b * Hn * LP;
    int l = l0 + lane;
    if (l < Ln) {
        float m = mu[lane], s = sc[lane];
#pragma unroll
        for (int hi = 0; hi < 32; hi++) {
            int h = wid * 32 + hi;
            Zb[(size_t)h * LP + l] = (tile[lane][h] - m) * s * g[h] + bb[h];
        }
    }
}

// ---------------- stage 1: q[b,c,:] = u_chunk @ W1  (M=640,N=64,K=128) ----------------
__global__ __launch_bounds__(256) void st1_kernel(int layer)
{
    int h  = blockIdx.y;
    int m0 = blockIdx.x * 128;
    __shared__ float As[32][132];
    __shared__ float Bs[32][68];
    int tid = threadIdx.x, lane = tid & 31, wid = tid >> 5;
    int wm = wid & 3, wn = wid >> 2;        // warp tile 32(M) x 32(N)
    float acc[2][4][4];
#pragma unroll
    for (int a = 0; a < 2; a++)
#pragma unroll
        for (int c = 0; c < 4; c++)
#pragma unroll
            for (int d = 0; d < 4; d++) acc[a][c][d] = 0.f;

    const float* W1p = d_W1 + (size_t)(layer * Hn + h) * (Tc * 64);
    int tg = lane & 3, gp = lane >> 2;
    int row = m0 + (tid >> 1);
    int bb = row / Cc, cc = row % Cc;
    const float* Arow = d_Zt + ((size_t)(bb * Hn + h)) * LP + cc * Tc;
    int half = tid & 1;

    for (int kt = 0; kt < 128; kt += 32) {
#pragma unroll
        for (int f = 0; f < 4; f++) {
            int k = half * 16 + f * 4;
            float4 v = *(const float4*)(Arow + kt + k);
            int m = tid >> 1;
            As[k][m]     = to_tf32(v.x);
            As[k + 1][m] = to_tf32(v.y);
            As[k + 2][m] = to_tf32(v.z);
            As[k + 3][m] = to_tf32(v.w);
        }
        {
            int k = tid >> 3, seg = tid & 7;
#pragma unroll
            for (int jj = 0; jj < 2; jj++) {
                int n = (seg + 8 * jj) * 4;
                *(float4*)&Bs[k][n] = *(const float4*)(W1p + (kt + k) * 64 + n);
            }
        }
        __syncthreads();
#pragma unroll
        for (int ks = 0; ks < 32; ks += 8) {
            uint32_t af[2][4], bf[4][2];
#pragma unroll
            for (int mi = 0; mi < 2; mi++) {
                int mb = wm * 32 + mi * 16;
                af[mi][0] = __float_as_uint(As[ks + tg    ][mb + gp    ]);
                af[mi][1] = __float_as_uint(As[ks + tg    ][mb + gp + 8]);
                af[mi][2] = __float_as_uint(As[ks + tg + 4][mb + gp    ]);
                af[mi][3] = __float_as_uint(As[ks + tg + 4][mb + gp + 8]);
            }
#pragma unroll
            for (int ni = 0; ni < 4; ni++) {
                int nb = wn * 32 + ni * 8;
                bf[ni][0] = __float_as_uint(Bs[ks + tg    ][nb + gp]);
                bf[ni][1] = __float_as_uint(Bs[ks + tg + 4][nb + gp]);
            }
#pragma unroll
            for (int mi = 0; mi < 2; mi++)
#pragma unroll
                for (int ni = 0; ni < 4; ni++)
                    mma_tf32(acc[mi][ni], af[mi], bf[ni]);
        }
        __syncthreads();
    }

#pragma unroll
    for (int mi = 0; mi < 2; mi++) {
#pragma unroll
        for (int ni = 0; ni < 4; ni++) {
            int n = wn * 32 + ni * 8 + tg * 2;
#pragma unroll
            for (int hf = 0; hf < 2; hf++) {
                int grow = m0 + wm * 32 + mi * 16 + gp + hf * 8;
                int b2 = grow / Cc, c2 = grow % Cc;
                size_t addr = ((size_t)(b2 * Hn + h) * Cc + c2) * 64 + n;
                d_Q[addr]     = acc[mi][ni][hf * 2];
                d_Q[addr + 1] = acc[mi][ni][hf * 2 + 1];
            }
        }
    }
}

// ---------------- stage 2: serial state pass over chunks ----------------
__global__ __launch_bounds__(256) void st2_kernel(int layer)
{
    int t = blockIdx.x * 256 + threadIdx.x;   // 131072
    int n = t & 31;
    int bh = t >> 5;                          // b*256+h
    int h = bh & 255;
    float2 lt = d_lamT[(layer * Hn + h) * 32 + n];
    const float* qp = d_Q + (size_t)bh * (Cc * 64);
    float* pp = d_P + (size_t)bh * (Cc * 64);
    float pr = 0.f, pi = 0.f;
    for (int c = 0; c < Cc; c++) {
        pp[c * 64 + n]      = pr;
        pp[c * 64 + 32 + n] = pi;
        float qr = qp[c * 64 + n], qi = qp[c * 64 + 32 + n];
        float prn = fmaf(lt.x, pr, fmaf(-lt.y, pi, qr));
        pi        = fmaf(lt.y, pr, fmaf( lt.x, pi, qi));
        pr = prn;
    }
}

// ---------------- stage 3: y = [u | p] @ [T_K+D | V], gelu -> Gt ----------------
__global__ __launch_bounds__(256) void st3_kernel(int layer)
{
    int h  = blockIdx.y;
    int m0 = blockIdx.x * 128;
    __shared__ float As[32][132];
    __shared__ float Bs[32][132];
    int tid = threadIdx.x, lane = tid & 31, wid = tid >> 5;
    int wm = wid & 3, wn = wid >> 2;          // warp tile 32(M) x 64(N)
    float acc[2][8][4];
#pragma unroll
    for (int a = 0; a < 2; a++)
#pragma unroll
        for (int c = 0; c < 8; c++)
#pragma unroll
            for (int d = 0; d < 4; d++) acc[a][c][d] = 0.f;

    const float* B3p = d_B3 + (size_t)(layer * Hn + h) * (192 * Tc);
    int tg = lane & 3, gp = lane >> 2;
    int row = m0 + (tid >> 1);
    int bb = row / Cc, cc = row % Cc;
    const float* Urow = d_Zt + ((size_t)(bb * Hn + h)) * LP + cc * Tc;
    const float* Prow = d_P + ((size_t)(bb * Hn + h) * Cc + cc) * 64;
    int half = tid & 1;

    for (int kt = 0; kt < 192; kt += 32) {
        const float* src = (kt < 128) ? (Urow + kt) : (Prow + (kt - 128));
#pragma unroll
        for (int f = 0; f < 4; f++) {
            int k = half * 16 + f * 4;
            float4 v = *(const float4*)(src + k);
            int m = tid >> 1;
            As[k][m]     = to_tf32(v.x);
            As[k + 1][m] = to_tf32(v.y);
            As[k + 2][m] = to_tf32(v.z);
            As[k + 3][m] = to_tf32(v.w);
        }
        {
            int k = tid >> 3, seg = tid & 7;
#pragma unroll
            for (int jj = 0; jj < 4; jj++) {
                int n = (seg + 8 * jj) * 4;
                *(float4*)&Bs[k][n] = *(const float4*)(B3p + (kt + k) * Tc + n);
            }
        }
        __syncthreads();
#pragma unroll
        for (int ks = 0; ks < 32; ks += 8) {
            uint32_t af[2][4], bf[8][2];
#pragma unroll
            for (int mi = 0; mi < 2; mi++) {
                int mb = wm * 32 + mi * 16;
                af[mi][0] = __float_as_uint(As[ks + tg    ][mb + gp    ]);
                af[mi][1] = __float_as_uint(As[ks + tg    ][mb + gp + 8]);
                af[mi][2] = __float_as_uint(As[ks + tg + 4][mb + gp    ]);
                af[mi][3] = __float_as_uint(As[ks + tg + 4][mb + gp + 8]);
            }
#pragma unroll
            for (int ni = 0; ni < 8; ni++) {
                int nb = wn * 64 + ni * 8;
                bf[ni][0] = __float_as_uint(Bs[ks + tg    ][nb + gp]);
                bf[ni][1] = __float_as_uint(Bs[ks + tg + 4][nb + gp]);
            }
#pragma unroll
            for (int mi = 0; mi < 2; mi++)
#pragma unroll
                for (int ni = 0; ni < 8; ni++)
                    mma_tf32(acc[mi][ni], af[mi], bf[ni]);
        }
        __syncthreads();
    }

#pragma unroll
    for (int mi = 0; mi < 2; mi++) {
#pragma unroll
        for (int ni = 0; ni < 8; ni++) {
            int i = wn * 64 + ni * 8 + tg * 2;
#pragma unroll
            for (int hf = 0; hf < 2; hf++) {
                int grow = m0 + wm * 32 + mi * 16 + gp + hf * 8;
                int b2 = grow / Cc, c2 = grow % Cc;
                float* Grow = d_Gt + ((size_t)(b2 * Hn + h)) * LP + c2 * Tc;
                Grow[i]     = gelu_tanh(acc[mi][ni][hf * 2]);
                Grow[i + 1] = gelu_tanh(acc[mi][ni][hf * 2 + 1]);
            }
        }
    }
}

// ---------------- GLU GEMM (tf32 mma) + bias + GLU + residual ----------------
__global__ __launch_bounds__(256) void glu_gemm_kernel(int layer)
{
    const int m0 = blockIdx.x * 128;
    const int n0 = blockIdx.y * 128;
    const int b  = blockIdx.z;
    __shared__ float As[32][132];
    __shared__ float Bs[32][132];
    int tid = threadIdx.x;
    int lane = tid & 31, wid = tid >> 5;
    int wm = wid & 3, wn = wid >> 2;
    float acc[2][8][4];
#pragma unroll
    for (int a = 0; a < 2; a++)
#pragma unroll
        for (int c = 0; c < 8; c++)
#pragma unroll
            for (int d = 0; d < 4; d++) acc[a][c][d] = 0.f;

    const float* Ag = d_Gt + (size_t)b * (Hn * LP);
    const float* Bg = d_W2 + (size_t)layer * (Hn * 2 * Hn);
    int tg = lane & 3, gp = lane >> 2;

    for (int kt = 0; kt < Hn; kt += 32) {
#pragma unroll
        for (int i = 0; i < 16; i++) {
            int idx = tid + i * 256;
            int k = idx >> 7, m = idx & 127;
            int gl = m0 + m;
            float v = (gl < Ln) ? Ag[(size_t)(kt + k) * LP + gl] : 0.f;
            As[k][m] = to_tf32(v);
        }
#pragma unroll
        for (int i = 0; i < 16; i++) {
            int idx = tid + i * 256;
            int k = idx >> 7, n = idx & 127;
            Bs[k][n] = to_tf32(Bg[(kt + k) * 512 + n0 + n]);
        }
        __syncthreads();
#pragma unroll
        for (int ks = 0; ks < 32; ks += 8) {
            uint32_t af[2][4], bf[8][2];
#pragma unroll
            for (int mi = 0; mi < 2; mi++) {
                int mb = wm * 32 + mi * 16;
                af[mi][0] = __float_as_uint(As[ks + tg    ][mb + gp    ]);
                af[mi][1] = __float_as_uint(As[ks + tg    ][mb + gp + 8]);
                af[mi][2] = __float_as_uint(As[ks + tg + 4][mb + gp    ]);
                af[mi][3] = __float_as_uint(As[ks + tg + 4][mb + gp + 8]);
            }
#pragma unroll
            for (int ni = 0; ni < 8; ni++) {
                int nb = wn * 64 + ni * 8;
                bf[ni][0] = __float_as_uint(Bs[ks + tg    ][nb + gp]);
                bf[ni][1] = __float_as_uint(Bs[ks + tg + 4][nb + gp]);
            }
#pragma unroll
            for (int mi = 0; mi < 2; mi++)
#pragma unroll
                for (int ni = 0; ni < 8; ni++)
                    mma_tf32(acc[mi][ni], af[mi], bf[ni]);
        }
        __syncthreads();
    }

    const float* Zb  = d_Zt + (size_t)b * (Hn * LP);
    const float* b2p = d_b2 + layer * 512;
#pragma unroll
    for (int mi = 0; mi < 2; mi++) {
        int mrow = wm * 32 + mi * 16 + gp;
#pragma unroll
        for (int ni = 0; ni < 8; ni++) {
            int nc = wn * 64 + ni * 8 + tg * 2;
            int j  = (n0 + nc) >> 1;
            float ba = b2p[n0 + nc], bg = b2p[n0 + nc + 1];
#pragma unroll
            for (int hf = 0; hf < 2; hf++) {
                int l = m0 + mrow + hf * 8;
                if (l < Ln) {
                    float a    = acc[mi][ni][hf * 2 + 0] + ba;
                    float gate = acc[mi][ni][hf * 2 + 1] + bg;
                    float o = a * (1.f / (1.f + expf(-gate)));
                    o += Zb[(size_t)j * LP + l];
                    d_X[((size_t)b * Ln + l) * Hn + j] = o;
                }
            }
        }
    }
}

// ---------------- final LayerNorm -> d_out ----------------
__global__ __launch_bounds__(256) void final_ln(
    const float* __restrict__ g, const float* __restrict__ bb, float* __restrict__ out)
{
    int lane = threadIdx.x & 31, wid = threadIdx.x >> 5;
    size_t row = (size_t)blockIdx.x * 8 + wid;
    const float* xr = d_X + row * Hn;
    float v[8], s = 0.f, q = 0.f;
#pragma unroll
    for (int k = 0; k < 8; k++) {
        v[k] = xr[k * 32 + lane];
        s += v[k]; q += v[k] * v[k];
    }
#pragma unroll
    for (int o = 16; o; o >>= 1) {
        s += __shfl_xor_sync(0xffffffffu, s, o);
        q += __shfl_xor_sync(0xffffffffu, q, o);
    }
    float m  = s * (1.f / 256.f);
    float sc = rsqrtf(q * (1.f / 256.f) - m * m + 1e-5f);
#pragma unroll
    for (int k = 0; k < 8; k++) {
        int h = k * 32 + lane;
        out[row * Hn + h] = (v[k] - m) * sc * g[h] + bb[h];
    }
}

// ---------------- launch ----------------
extern "C" void kernel_launch(void* const* d_in, const int* in_sizes, int n_in,
                              void* d_out, int out_size)
{
    const float* x       = (const float*)d_in[0];
    const float* W_in    = (const float*)d_in[1];
    const float* b_in    = (const float*)d_in[2];
    const float* ln_g    = (const float*)d_in[3];
    const float* ln_b    = (const float*)d_in[4];
    const float* log_dt  = (const float*)d_in[5];
    const float* logA_re = (const float*)d_in[6];
    const float* A_im    = (const float*)d_in[7];
    const float* Cp      = (const float*)d_in[8];
    const float* Dp      = (const float*)d_in[9];
    const float* W_glu   = (const float*)d_in[10];
    const float* b_glu   = (const float*)d_in[11];
    const float* fn_g    = (const float*)d_in[12];
    const float* fn_b    = (const float*)d_in[13];
    float* out = (float*)d_out;

    prep_ssm<<<128, 256>>>(log_dt, logA_re, A_im, Cp);
    prep_pow<<<128, 256>>>();
    prep_tk<<<NLn * Hn, 128>>>(Dp);
    prep_w2<<<1024, 256>>>(W_glu, b_glu);
    in_proj<<<2500, 256>>>(x, W_in, b_in);

    for (int i = 0; i < NLn; i++) {
        dim3 gln((Ln + 31) / 32, Bn);
        ln_t_kernel<<<gln, 256>>>(i, ln_g, ln_b);
        st1_kernel<<<dim3(5, Hn), 256>>>(i);
        st2_kernel<<<512, 256>>>(i);
        st3_kernel<<<dim3(5, Hn), 256>>>(i);
        dim3 gg((Ln + 127) / 128, 4, Bn);
        glu_gemm_kernel<<<gg, 256>>>(i);
    }
    final_ln<<<(Bn * Ln) / 8, 256>>>(fn_g, fn_b, out);
}

// round 3
// speedup vs baseline: 1.6395x; 1.3765x over previous
#include <cuda_runtime.h>
#include <cstdint>
#include <math.h>

#define Bn   16
#define Ln   5000
#define Hn   256
#define Nn   32
#define NLn  4
#define DINn 12
#define Tc   128          // chunk length
#define Cc   40           // chunks (padded length 5120)
#define LP   5120         // padded L
#define Mrows (Bn * Cc)   // 640 chunk-rows

// ---------------- scratch (device globals; zero-initialized) ----------------
__device__ __align__(16) float  d_X  [(size_t)Bn * Ln * Hn];   // activations (B, L, H)
__device__ __align__(16) float  d_Zt [(size_t)Bn * Hn * LP];   // LN output fp32 (residual), pad=0
__device__ __align__(16) float  d_Ztr[(size_t)Bn * Hn * LP];   // LN output tf32-rounded, pad=0
__device__ __align__(16) float  d_Gt [(size_t)Bn * Hn * LP];   // tf32(gelu(y)), (B, H, Lpad)
__device__ __align__(16) float4 d_SSMP[NLn * Hn * Nn];         // (lam_re, lam_im, 2Ct_re, 2Ct_im)
__device__ __align__(16) float  d_W2[NLn * Hn * 2 * Hn];       // tf32(W_glu) interleaved halves
__device__ __align__(16) float  d_b2[NLn * 2 * Hn];
__device__ __align__(16) float  d_Q  [(size_t)Bn * Hn * Cc * 64];   // chunk state contributions
__device__ __align__(16) float  d_Pt2[(size_t)Hn * Mrows * 64];     // tf32 chunk-start states [h][m][n]
__device__ __align__(16) float  d_W1[(size_t)NLn * Hn * Tc * 64];   // stage-1 B (tf32)
__device__ __align__(16) float  d_B3[(size_t)NLn * Hn * 192 * Tc];  // stage-3 B (tf32)
__device__ __align__(16) float  d_Kv[NLn * Hn * Tc];
__device__ __align__(16) float2 d_lamT[NLn * Hn * Nn];              // lambda^128

// ---------------- helpers ----------------
__device__ __forceinline__ float to_tf32(float x) {
    uint32_t u;
    asm("cvt.rna.tf32.f32 %0, %1;" : "=r"(u) : "f"(x));
    return __uint_as_float(u);
}

__device__ __forceinline__ void cp16(float* dst, const float* src) {
    uint32_t d = (uint32_t)__cvta_generic_to_shared(dst);
    asm volatile("cp.async.cg.shared.global [%0], [%1], 16;\n" :: "r"(d), "l"(src));
}
__device__ __forceinline__ void cp_commit() {
    asm volatile("cp.async.commit_group;\n");
}
template <int N>
__device__ __forceinline__ void cp_wait() {
    asm volatile("cp.async.wait_group %0;\n" :: "n"(N));
}

__device__ __forceinline__ void mma_tf32(float* d, const uint32_t* a, const uint32_t* b) {
    asm volatile(
        "mma.sync.aligned.m16n8k8.row.col.f32.tf32.tf32.f32 "
        "{%0,%1,%2,%3}, {%4,%5,%6,%7}, {%8,%9}, {%0,%1,%2,%3};\n"
        : "+f"(d[0]), "+f"(d[1]), "+f"(d[2]), "+f"(d[3])
        : "r"(a[0]), "r"(a[1]), "r"(a[2]), "r"(a[3]), "r"(b[0]), "r"(b[1]));
}

__device__ __forceinline__ float gelu_tanh(float x) {
    float x3 = x * x * x;
    return 0.5f * x * (1.f + tanhf(0.7978845608028654f * fmaf(0.044715f, x3, x)));
}

// ---------------- param prep ----------------
__global__ __launch_bounds__(256) void prep_ssm(
    const float* __restrict__ log_dt, const float* __restrict__ logA_re,
    const float* __restrict__ A_im,   const float* __restrict__ Cp)
{
    int idx = blockIdx.x * 256 + threadIdx.x;      // NL*H*N = 32768
    int i = idx / (Hn * Nn);
    int h = (idx / Nn) % Hn;
    float dt  = expf(log_dt[i * Hn + h]);
    float aRe = -expf(logA_re[idx]);
    float aIm = A_im[idx];
    float er  = expf(aRe * dt);
    float ang = aIm * dt;
    float lr = er * cosf(ang), li = er * sinf(ang);
    float nr = lr - 1.f, ni = li;
    float inv = 1.f / (aRe * aRe + aIm * aIm);
    float qr = (nr * aRe + ni * aIm) * inv;
    float qi = (ni * aRe - nr * aIm) * inv;
    float cr = Cp[2 * idx], ci = Cp[2 * idx + 1];
    float Ctr = cr * qr - ci * qi;
    float Cti = cr * qi + ci * qr;
    d_SSMP[idx] = make_float4(lr, li, 2.f * Ctr, 2.f * Cti);
}

// powers of lambda -> W1 (stage1 B), V rows of B3, lamT, K vector
__global__ __launch_bounds__(256) void prep_pow()
{
    int gw = blockIdx.x * 8 + (threadIdx.x >> 5);   // 0..1023 = layer*256+h
    int n  = threadIdx.x & 31;
    float4 p = d_SSMP[gw * 32 + n];
    float lr = p.x, li = p.y, tcr = p.z, tci = p.w;
    float curr = 1.f, curi = 0.f;                    // lambda^j
    float* W1p = d_W1 + (size_t)gw * (Tc * 64);
    float* B3p = d_B3 + (size_t)gw * (192 * Tc);
    float* Kvp = d_Kv + gw * Tc;
    for (int j = 0; j <= 128; j++) {
        if (j < 128) {
            float kr = tcr * curr - tci * curi;
            float ki = tcr * curi + tci * curr;
            W1p[(127 - j) * 64 + n]      = to_tf32(kr);
            W1p[(127 - j) * 64 + 32 + n] = to_tf32(ki);
            float s = kr;
#pragma unroll
            for (int o = 16; o; o >>= 1) s += __shfl_xor_sync(0xffffffffu, s, o);
            if (n == 0) Kvp[j] = s;
        }
        if (j >= 1) {
            int i = j - 1;
            B3p[(128 + n) * Tc + i] = to_tf32(curr);    //  Re(lambda^{i+1})
            B3p[(160 + n) * Tc + i] = to_tf32(-curi);   // -Im(lambda^{i+1})
        }
        if (j == 128) d_lamT[gw * 32 + n] = make_float2(curr, curi);
        float nr2 = curr * lr - curi * li;
        curi = curr * li + curi * lr;
        curr = nr2;
    }
}

// Toeplitz rows of B3 (with D folded into the diagonal)
__global__ __launch_bounds__(128) void prep_tk(const float* __restrict__ Dp)
{
    int gw = blockIdx.x;          // layer*256+h
    int i  = threadIdx.x;         // 0..127
    __shared__ float Ks[Tc];
    Ks[i] = d_Kv[gw * Tc + i];
    __syncthreads();
    float Dh = Dp[gw];
    float* B3p = d_B3 + (size_t)gw * (192 * Tc);
    for (int j = 0; j < 128; j++) {
        float v = 0.f;
        if (i >= j) v = Ks[i - j] + (i == j ? Dh : 0.f);
        B3p[j * Tc + i] = to_tf32(v);
    }
}

__global__ __launch_bounds__(256) void prep_w2(
    const float* __restrict__ W_glu, const float* __restrict__ b_glu)
{
    int idx = blockIdx.x * 256 + threadIdx.x;      // NL*H*256 = 262144
    int i = idx >> 16;
    int rem = idx & 65535;
    int h = rem >> 8;
    int j = rem & 255;
    const float* src = W_glu + ((size_t)i * Hn + h) * (2 * Hn);
    float* dst = d_W2 + ((size_t)i * Hn + h) * (2 * Hn);
    dst[2 * j]     = to_tf32(src[j]);
    dst[2 * j + 1] = to_tf32(src[j + Hn]);
    if (idx < NLn * Hn) {
        int i2 = idx >> 8, j2 = idx & 255;
        d_b2[i2 * 512 + 2 * j2]     = b_glu[i2 * 512 + j2];
        d_b2[i2 * 512 + 2 * j2 + 1] = b_glu[i2 * 512 + Hn + j2];
    }
}

// ---------------- input projection ----------------
__global__ __launch_bounds__(256) void in_proj(
    const float* __restrict__ x, const float* __restrict__ W, const float* __restrict__ bias)
{
    __shared__ float xs[32][DINn];
    int tid = threadIdx.x;
    int r0 = blockIdx.x * 32;
    for (int t = tid; t < 32 * DINn; t += 256)
        xs[t / DINn][t % DINn] = x[(size_t)r0 * DINn + t];
    float w[DINn];
#pragma unroll
    for (int k = 0; k < DINn; k++) w[k] = W[k * Hn + tid];
    float bv = bias[tid];
    __syncthreads();
#pragma unroll 4
    for (int r = 0; r < 32; r++) {
        float a = bv;
#pragma unroll
        for (int k = 0; k < DINn; k++) a = fmaf(xs[r][k], w[k], a);
        d_X[((size_t)(r0 + r)) * Hn + tid] = a;
    }
}

// ---------------- LayerNorm + transpose to (B, H, Lpad); writes fp32 + tf32 copies ---
__global__ __launch_bounds__(256) void ln_t_kernel(
    int layer, const float* __restrict__ ln_g, const float* __restrict__ ln_b)
{
    __shared__ float tile[32][257];
    __shared__ float mu[32], sc[32];
    int b  = blockIdx.y;
    int l0 = blockIdx.x * 32;
    int tid = threadIdx.x, lane = tid & 31, wid = tid >> 5;
    const float* Xb = d_X + (size_t)b * Ln * Hn;
#pragma unroll
    for (int r = 0; r < 32; r++) {
        int l = l0 + r;
        tile[r][tid] = (l < Ln) ? Xb[(size_t)l * Hn + tid] : 0.f;
    }
    __syncthreads();
#pragma unroll
    for (int rr = 0; rr < 4; rr++) {
        int r = wid * 4 + rr;
        float s = 0.f, q = 0.f;
#pragma unroll
        for (int k = 0; k < 8; k++) {
            float v = tile[r][k * 32 + lane];
            s += v; q += v * v;
        }
#pragma unroll
        for (int o = 16; o; o >>= 1) {
            s += __shfl_xor_sync(0xffffffffu, s, o);
            q += __shfl_xor_sync(0xffffffffu, q, o);
        }
        if (lane == 0) {
            float m = s * (1.f / 256.f);
            float v = q * (1.f / 256.f) - m * m;
            mu[r] = m;
            sc[r] = rsqrtf(v + 1e-5f);
        }
    }
    __syncthreads();
    const float* g  = ln_g + layer * Hn;
    const float* bb = ln_b + layer * Hn;
    float* Zb  = d_Zt  + (size_t)b * Hn * LP;
    float* Zrb = d_Ztr + (size_t)b * Hn * LP;
    int l = l0 + lane;
    if (l < Ln) {
        float m = mu[lane], s = sc[lane];
#pragma unroll
        for (int hi = 0; hi < 32; hi++) {
            int h = wid * 32 + hi;
            float zv = (tile[lane][h] - m) * s * g[h] + bb[h];
            Zb [(size_t)h * LP + l] = zv;
            Zrb[(size_t)h * LP + l] = to_tf32(zv);
        }
    }
}

// ---------------- stage 1: q = u_chunk @ W1  (M=640, N=64, K=128), pipelined --------
__global__ __launch_bounds__(256) void st1_kernel(int layer)
{
    extern __shared__ float sm[];
    float* As = sm;                   // 2 bufs [128][36]
    float* Bs = sm + 2 * 128 * 36;    // 2 bufs [32][72]
    int h  = blockIdx.y;
    int m0 = blockIdx.x * 128;
    int tid = threadIdx.x, lane = tid & 31, wid = tid >> 5;
    int wm = wid & 3, wn = wid >> 2;        // warp tile 32(M) x 32(N)
    int tg = lane & 3, gp = lane >> 2;

    // A copy lanes: rows mA + i*32, k-offset sA
    int mA = tid >> 3;
    int sA = (tid & 7) * 4;
    const float* baseU[4];
#pragma unroll
    for (int i = 0; i < 4; i++) {
        int gm = m0 + mA + i * 32;
        int bb = gm / Cc, cc = gm % Cc;
        baseU[i] = d_Ztr + ((size_t)(bb * Hn + h)) * LP + cc * Tc + sA;
    }
    // B copy lanes
    int kB = tid >> 4;                 // 0..15 (+16)
    int sB = (tid & 15) * 4;
    const float* W1p = d_W1 + (size_t)(layer * Hn + h) * (Tc * 64);

    float acc[2][4][4] = {};

    auto fill = [&](int s) {
        float* dA = As + (s & 1) * (128 * 36);
        const float* sAa[4];
#pragma unroll
        for (int i = 0; i < 4; i++) sAa[i] = baseU[i] + s * 32;
#pragma unroll
        for (int i = 0; i < 4; i++)
            cp16(dA + (mA + i * 32) * 36 + sA, sAa[i]);
        float* dB = Bs + (s & 1) * (32 * 72);
        const float* sBb = W1p + (size_t)(s * 32) * 64 + sB;
#pragma unroll
        for (int i = 0; i < 2; i++)
            cp16(dB + (kB + i * 16) * 72 + sB, sBb + (size_t)(kB + i * 16) * 64);
    };

    fill(0); cp_commit();
#pragma unroll
    for (int s = 0; s < 4; s++) {
        if (s + 1 < 4) { fill(s + 1); cp_commit(); cp_wait<1>(); }
        else cp_wait<0>();
        __syncthreads();
        const float* a  = As + (s & 1) * (128 * 36);
        const float* bp = Bs + (s & 1) * (32 * 72);
#pragma unroll
        for (int ks = 0; ks < 32; ks += 8) {
            uint32_t af[2][4], bf[4][2];
#pragma unroll
            for (int mi = 0; mi < 2; mi++) {
                int mb = wm * 32 + mi * 16;
                af[mi][0] = __float_as_uint(a[(mb + gp    ) * 36 + ks + tg    ]);
                af[mi][1] = __float_as_uint(a[(mb + gp + 8) * 36 + ks + tg    ]);
                af[mi][2] = __float_as_uint(a[(mb + gp    ) * 36 + ks + tg + 4]);
                af[mi][3] = __float_as_uint(a[(mb + gp + 8) * 36 + ks + tg + 4]);
            }
#pragma unroll
            for (int ni = 0; ni < 4; ni++) {
                int nb = wn * 32 + ni * 8;
                bf[ni][0] = __float_as_uint(bp[(ks + tg    ) * 72 + nb + gp]);
                bf[ni][1] = __float_as_uint(bp[(ks + tg + 4) * 72 + nb + gp]);
            }
#pragma unroll
            for (int mi = 0; mi < 2; mi++)
#pragma unroll
                for (int ni = 0; ni < 4; ni++)
                    mma_tf32(acc[mi][ni], af[mi], bf[ni]);
        }
        __syncthreads();
    }

#pragma unroll
    for (int mi = 0; mi < 2; mi++) {
#pragma unroll
        for (int ni = 0; ni < 4; ni++) {
            int n = wn * 32 + ni * 8 + tg * 2;
#pragma unroll
            for (int hf = 0; hf < 2; hf++) {
                int grow = m0 + wm * 32 + mi * 16 + gp + hf * 8;
                int b2 = grow / Cc, c2 = grow % Cc;
                size_t addr = ((size_t)(b2 * Hn + h) * Cc + c2) * 64 + n;
                d_Q[addr]     = acc[mi][ni][hf * 2];
                d_Q[addr + 1] = acc[mi][ni][hf * 2 + 1];
            }
        }
    }
}

// ---------------- stage 2: serial state pass over chunks -> Pt2[h][m][n] (tf32) -----
__global__ __launch_bounds__(256) void st2_kernel(int layer)
{
    int t = blockIdx.x * 256 + threadIdx.x;   // 131072
    int n = t & 31;
    int bh = t >> 5;                          // b*256+h
    int h = bh & 255, b = bh >> 8;
    float2 lt = d_lamT[(layer * Hn + h) * 32 + n];
    const float* qp = d_Q + (size_t)bh * (Cc * 64);
    float* pp = d_Pt2 + ((size_t)h * Mrows + b * Cc) * 64;
    float pr = 0.f, pi = 0.f;
    for (int c = 0; c < Cc; c++) {
        pp[c * 64 + n]      = to_tf32(pr);
        pp[c * 64 + 32 + n] = to_tf32(pi);
        float qr = qp[c * 64 + n], qi = qp[c * 64 + 32 + n];
        float prn = fmaf(lt.x, pr, fmaf(-lt.y, pi, qr));
        pi        = fmaf(lt.y, pr, fmaf( lt.x, pi, qi));
        pr = prn;
    }
}

// ---------------- stage 3: y = [u | p] @ [T_K+D | V], gelu -> Gt (tf32), pipelined --
__global__ __launch_bounds__(256) void st3_kernel(int layer)
{
    extern __shared__ float sm[];
    float* As = sm;                   // 2 bufs [128][36]
    float* Bs = sm + 2 * 128 * 36;    // 2 bufs [32][136]
    int h  = blockIdx.y;
    int m0 = blockIdx.x * 128;
    int tid = threadIdx.x, lane = tid & 31, wid = tid >> 5;
    int wm = wid & 3, wn = wid >> 2;          // warp tile 32(M) x 64(N)
    int tg = lane & 3, gp = lane >> 2;

    int mA = tid >> 3;
    int sA = (tid & 7) * 4;
    const float* baseU[4];
    const float* baseP[4];
#pragma unroll
    for (int i = 0; i < 4; i++) {
        int gm = m0 + mA + i * 32;
        int bb = gm / Cc, cc = gm % Cc;
        baseU[i] = d_Ztr + ((size_t)(bb * Hn + h)) * LP + cc * Tc + sA;
        baseP[i] = d_Pt2 + ((size_t)h * Mrows + gm) * 64 + sA;
    }
    int kB = tid >> 5;                 // 0..7 (+8,16,24)
    int sB = (tid & 31) * 4;
    const float* B3p = d_B3 + (size_t)(layer * Hn + h) * (192 * Tc) + sB;

    float acc[2][8][4] = {};

    auto fill = [&](int s) {
        int kt = s * 32;
        float* dA = As + (s & 1) * (128 * 36);
#pragma unroll
        for (int i = 0; i < 4; i++) {
            const float* src = (kt < 128) ? (baseU[i] + kt) : (baseP[i] + (kt - 128));
            cp16(dA + (mA + i * 32) * 36 + sA, src);
        }
        float* dB = Bs + (s & 1) * (32 * 136);
        const float* sBb = B3p + (size_t)kt * Tc;
#pragma unroll
        for (int i = 0; i < 4; i++)
            cp16(dB + (kB + i * 8) * 136 + sB, sBb + (size_t)(kB + i * 8) * Tc);
    };

    fill(0); cp_commit();
#pragma unroll
    for (int s = 0; s < 6; s++) {
        if (s + 1 < 6) { fill(s + 1); cp_commit(); cp_wait<1>(); }
        else cp_wait<0>();
        __syncthreads();
        const float* a  = As + (s & 1) * (128 * 36);
        const float* bp = Bs + (s & 1) * (32 * 136);
#pragma unroll
        for (int ks = 0; ks < 32; ks += 8) {
            uint32_t af[2][4], bf[8][2];
#pragma unroll
            for (int mi = 0; mi < 2; mi++) {
                int mb = wm * 32 + mi * 16;
                af[mi][0] = __float_as_uint(a[(mb + gp    ) * 36 + ks + tg    ]);
                af[mi][1] = __float_as_uint(a[(mb + gp + 8) * 36 + ks + tg    ]);
                af[mi][2] = __float_as_uint(a[(mb + gp    ) * 36 + ks + tg + 4]);
                af[mi][3] = __float_as_uint(a[(mb + gp + 8) * 36 + ks + tg + 4]);
            }
#pragma unroll
            for (int ni = 0; ni < 8; ni++) {
                int nb = wn * 64 + ni * 8;
                bf[ni][0] = __float_as_uint(bp[(ks + tg    ) * 136 + nb + gp]);
                bf[ni][1] = __float_as_uint(bp[(ks + tg + 4) * 136 + nb + gp]);
            }
#pragma unroll
            for (int mi = 0; mi < 2; mi++)
#pragma unroll
                for (int ni = 0; ni < 8; ni++)
                    mma_tf32(acc[mi][ni], af[mi], bf[ni]);
        }
        __syncthreads();
    }

#pragma unroll
    for (int mi = 0; mi < 2; mi++) {
#pragma unroll
        for (int ni = 0; ni < 8; ni++) {
            int i = wn * 64 + ni * 8 + tg * 2;
#pragma unroll
            for (int hf = 0; hf < 2; hf++) {
                int grow = m0 + wm * 32 + mi * 16 + gp + hf * 8;
                int b2 = grow / Cc, c2 = grow % Cc;
                float* Grow = d_Gt + ((size_t)(b2 * Hn + h)) * LP + c2 * Tc;
                Grow[i]     = to_tf32(gelu_tanh(acc[mi][ni][hf * 2]));
                Grow[i + 1] = to_tf32(gelu_tanh(acc[mi][ni][hf * 2 + 1]));
            }
        }
    }
}

// ---------------- GLU GEMM (pipelined tf32) + bias + GLU + residual -----------------
__global__ __launch_bounds__(256) void glu_gemm_kernel(int layer)
{
    extern __shared__ float sm[];
    float* As = sm;                  // 2 bufs [32][136]
    float* Bs = sm + 2 * 32 * 136;   // 2 bufs [32][136]
    const int m0 = blockIdx.x * 128;
    const int n0 = blockIdx.y * 128;
    const int b  = blockIdx.z;
    int tid = threadIdx.x, lane = tid & 31, wid = tid >> 5;
    int wm = wid & 3, wn = wid >> 2;
    int tg = lane & 3, gp = lane >> 2;

    int kr = tid >> 5;                // 0..7 (+8,16,24)
    int sf = (tid & 31) * 4;
    const float* Ag = d_Gt + (size_t)b * (Hn * LP) + m0 + sf;
    const float* Bg = d_W2 + (size_t)layer * (Hn * 512) + n0 + sf;

    float acc[2][8][4] = {};

    auto fill = [&](int s) {
        float* dA = As + (s & 1) * (32 * 136);
        float* dB = Bs + (s & 1) * (32 * 136);
        const float* sAa = Ag + (size_t)(s * 32 + kr) * LP;
        const float* sBb = Bg + (size_t)(s * 32 + kr) * 512;
#pragma unroll
        for (int i = 0; i < 4; i++) {
            cp16(dA + (kr + i * 8) * 136 + sf, sAa + (size_t)i * 8 * LP);
            cp16(dB + (kr + i * 8) * 136 + sf, sBb + (size_t)i * 8 * 512);
        }
    };

    fill(0); cp_commit();
#pragma unroll
    for (int s = 0; s < 8; s++) {
        if (s + 1 < 8) { fill(s + 1); cp_commit(); cp_wait<1>(); }
        else cp_wait<0>();
        __syncthreads();
        const float* a  = As + (s & 1) * (32 * 136);
        const float* bp = Bs + (s & 1) * (32 * 136);
#pragma unroll
        for (int ks = 0; ks < 32; ks += 8) {
            uint32_t af[2][4], bf[8][2];
#pragma unroll
            for (int mi = 0; mi < 2; mi++) {
                int mb = wm * 32 + mi * 16;
                af[mi][0] = __float_as_uint(a[(ks + tg    ) * 136 + mb + gp    ]);
                af[mi][1] = __float_as_uint(a[(ks + tg    ) * 136 + mb + gp + 8]);
                af[mi][2] = __float_as_uint(a[(ks + tg + 4) * 136 + mb + gp    ]);
                af[mi][3] = __float_as_uint(a[(ks + tg + 4) * 136 + mb + gp + 8]);
            }
#pragma unroll
            for (int ni = 0; ni < 8; ni++) {
                int nb = wn * 64 + ni * 8;
                bf[ni][0] = __float_as_uint(bp[(ks + tg    ) * 136 + nb + gp]);
                bf[ni][1] = __float_as_uint(bp[(ks + tg + 4) * 136 + nb + gp]);
            }
#pragma unroll
            for (int mi = 0; mi < 2; mi++)
#pragma unroll
                for (int ni = 0; ni < 8; ni++)
                    mma_tf32(acc[mi][ni], af[mi], bf[ni]);
        }
        __syncthreads();
    }

    const float* Zb  = d_Zt + (size_t)b * (Hn * LP);
    const float* b2p = d_b2 + layer * 512;
#pragma unroll
    for (int mi = 0; mi < 2; mi++) {
        int mrow = wm * 32 + mi * 16 + gp;
#pragma unroll
        for (int ni = 0; ni < 8; ni++) {
            int nc = wn * 64 + ni * 8 + tg * 2;
            int j  = (n0 + nc) >> 1;
            float ba = b2p[n0 + nc], bg = b2p[n0 + nc + 1];
#pragma unroll
            for (int hf = 0; hf < 2; hf++) {
                int l = m0 + mrow + hf * 8;
                if (l < Ln) {
                    float av   = acc[mi][ni][hf * 2 + 0] + ba;
                    float gate = acc[mi][ni][hf * 2 + 1] + bg;
                    float o = av * (1.f / (1.f + expf(-gate)));
                    o += Zb[(size_t)j * LP + l];
                    d_X[((size_t)b * Ln + l) * Hn + j] = o;
                }
            }
        }
    }
}

// ---------------- final LayerNorm -> d_out ----------------
__global__ __launch_bounds__(256) void final_ln(
    const float* __restrict__ g, const float* __restrict__ bb, float* __restrict__ out)
{
    int lane = threadIdx.x & 31, wid = threadIdx.x >> 5;
    size_t row = (size_t)blockIdx.x * 8 + wid;
    const float* xr = d_X + row * Hn;
    float v[8], s = 0.f, q = 0.f;
#pragma unroll
    for (int k = 0; k < 8; k++) {
        v[k] = xr[k * 32 + lane];
        s += v[k]; q += v[k] * v[k];
    }
#pragma unroll
    for (int o = 16; o; o >>= 1) {
        s += __shfl_xor_sync(0xffffffffu, s, o);
        q += __shfl_xor_sync(0xffffffffu, q, o);
    }
    float m  = s * (1.f / 256.f);
    float sc = rsqrtf(q * (1.f / 256.f) - m * m + 1e-5f);
#pragma unroll
    for (int k = 0; k < 8; k++) {
        int h = k * 32 + lane;
        out[row * Hn + h] = (v[k] - m) * sc * g[h] + bb[h];
    }
}

// ---------------- launch ----------------
extern "C" void kernel_launch(void* const* d_in, const int* in_sizes, int n_in,
                              void* d_out, int out_size)
{
    const float* x       = (const float*)d_in[0];
    const float* W_in    = (const float*)d_in[1];
    const float* b_in    = (const float*)d_in[2];
    const float* ln_g    = (const float*)d_in[3];
    const float* ln_b    = (const float*)d_in[4];
    const float* log_dt  = (const float*)d_in[5];
    const float* logA_re = (const float*)d_in[6];
    const float* A_im    = (const float*)d_in[7];
    const float* Cp      = (const float*)d_in[8];
    const float* Dp      = (const float*)d_in[9];
    const float* W_glu   = (const float*)d_in[10];
    const float* b_glu   = (const float*)d_in[11];
    const float* fn_g    = (const float*)d_in[12];
    const float* fn_b    = (const float*)d_in[13];
    float* out = (float*)d_out;

    const int smem_st1 = (2 * 128 * 36 + 2 * 32 * 72) * 4;    // 55296
    const int smem_st3 = (2 * 128 * 36 + 2 * 32 * 136) * 4;   // 71680
    const int smem_glu = (2 * 32 * 136 * 2) * 4;              // 69632
    cudaFuncSetAttribute(st1_kernel, cudaFuncAttributeMaxDynamicSharedMemorySize, smem_st1);
    cudaFuncSetAttribute(st3_kernel, cudaFuncAttributeMaxDynamicSharedMemorySize, smem_st3);
    cudaFuncSetAttribute(glu_gemm_kernel, cudaFuncAttributeMaxDynamicSharedMemorySize, smem_glu);

    prep_ssm<<<128, 256>>>(log_dt, logA_re, A_im, Cp);
    prep_pow<<<128, 256>>>();
    prep_tk<<<NLn * Hn, 128>>>(Dp);
    prep_w2<<<1024, 256>>>(W_glu, b_glu);
    in_proj<<<2500, 256>>>(x, W_in, b_in);

    for (int i = 0; i < NLn; i++) {
        dim3 gln((Ln + 31) / 32, Bn);
        ln_t_kernel<<<gln, 256>>>(i, ln_g, ln_b);
        st1_kernel<<<dim3(Mrows / 128, Hn), 256, smem_st1>>>(i);
        st2_kernel<<<512, 256>>>(i);
        st3_kernel<<<dim3(Mrows / 128, Hn), 256, smem_st3>>>(i);
        dim3 gg(LP / 128, 4, Bn);
        glu_gemm_kernel<<<gg, 256, smem_glu>>>(i);
    }
    final_ln<<<(Bn * Ln) / 8, 256>>>(fn_g, fn_b, out);
}

// round 4
// speedup vs baseline: 2.2249x; 1.3570x over previous
#include <cuda_runtime.h>
#include <cstdint>
#include <math.h>

#define Bn   16
#define Ln   5000
#define Hn   256
#define Nn   32
#define NLn  4
#define DINn 12
#define Tc   128          // chunk length
#define Cc   40           // chunks (padded length 5120)
#define LP   5120         // padded L
#define Mrows (Bn * Cc)   // 640 chunk-rows

// ---------------- scratch (device globals; zero-initialized) ----------------
__device__ __align__(16) float  d_X  [(size_t)Bn * Ln * Hn];   // activations (B, L, H)
__device__ __align__(16) float  d_Zt [(size_t)Bn * Hn * LP];   // LN output fp32 (residual), pad=0
__device__ __align__(16) float  d_Ztr[(size_t)Bn * Hn * LP];   // LN output tf32-rounded, pad=0
__device__ __align__(16) float  d_Gt [(size_t)Bn * Hn * LP];   // tf32(gelu(y)), (B, H, Lpad)
__device__ __align__(16) float4 d_SSMP[NLn * Hn * Nn];         // (lam_re, lam_im, 2Ct_re, 2Ct_im)
__device__ __align__(16) float  d_W2[NLn * Hn * 2 * Hn];       // tf32(W_glu) interleaved halves
__device__ __align__(16) float  d_b2[NLn * 2 * Hn];
__device__ __align__(16) float  d_Q  [(size_t)Bn * Hn * Cc * 64];   // chunk state contributions
__device__ __align__(16) float  d_Pt2[(size_t)Hn * Mrows * 64];     // tf32 chunk-start states [h][m][n]
__device__ __align__(16) float  d_W1[(size_t)NLn * Hn * Tc * 64];   // stage-1 B (tf32)
__device__ __align__(16) float  d_B3[(size_t)NLn * Hn * 192 * Tc];  // stage-3 B (tf32)
__device__ __align__(16) float  d_Kv[NLn * Hn * Tc];
__device__ __align__(16) float2 d_lamT[NLn * Hn * Nn];              // lambda^128

// ---------------- helpers ----------------
__device__ __forceinline__ float to_tf32(float x) {
    uint32_t u;
    asm("cvt.rna.tf32.f32 %0, %1;" : "=r"(u) : "f"(x));
    return __uint_as_float(u);
}

__device__ __forceinline__ void cp16(float* dst, const float* src) {
    uint32_t d = (uint32_t)__cvta_generic_to_shared(dst);
    asm volatile("cp.async.cg.shared.global [%0], [%1], 16;\n" :: "r"(d), "l"(src));
}
__device__ __forceinline__ void cp_commit() {
    asm volatile("cp.async.commit_group;\n");
}
template <int N>
__device__ __forceinline__ void cp_wait() {
    asm volatile("cp.async.wait_group %0;\n" :: "n"(N));
}

__device__ __forceinline__ void mma_tf32(float* d, const uint32_t* a, const uint32_t* b) {
    asm volatile(
        "mma.sync.aligned.m16n8k8.row.col.f32.tf32.tf32.f32 "
        "{%0,%1,%2,%3}, {%4,%5,%6,%7}, {%8,%9}, {%0,%1,%2,%3};\n"
        : "+f"(d[0]), "+f"(d[1]), "+f"(d[2]), "+f"(d[3])
        : "r"(a[0]), "r"(a[1]), "r"(a[2]), "r"(a[3]), "r"(b[0]), "r"(b[1]));
}

// exact tanh-gelu rewritten as x*sigmoid(2t); __expf error ~1e-6 (invisible under tf32)
__device__ __forceinline__ float gelu_fast(float x) {
    float t2 = 1.5957691216057308f * fmaf(0.044715f, x * x * x, x);
    return x * (1.f / (1.f + __expf(-t2)));
}

// ---------------- param prep ----------------
__global__ __launch_bounds__(256) void prep_ssm(
    const float* __restrict__ log_dt, const float* __restrict__ logA_re,
    const float* __restrict__ A_im,   const float* __restrict__ Cp)
{
    int idx = blockIdx.x * 256 + threadIdx.x;      // NL*H*N = 32768
    int i = idx / (Hn * Nn);
    int h = (idx / Nn) % Hn;
    float dt  = expf(log_dt[i * Hn + h]);
    float aRe = -expf(logA_re[idx]);
    float aIm = A_im[idx];
    float er  = expf(aRe * dt);
    float ang = aIm * dt;
    float lr = er * cosf(ang), li = er * sinf(ang);
    float nr = lr - 1.f, ni = li;
    float inv = 1.f / (aRe * aRe + aIm * aIm);
    float qr = (nr * aRe + ni * aIm) * inv;
    float qi = (ni * aRe - nr * aIm) * inv;
    float cr = Cp[2 * idx], ci = Cp[2 * idx + 1];
    float Ctr = cr * qr - ci * qi;
    float Cti = cr * qi + ci * qr;
    d_SSMP[idx] = make_float4(lr, li, 2.f * Ctr, 2.f * Cti);
}

// powers of lambda -> W1 (stage1 B), V rows of B3, lamT, K vector
__global__ __launch_bounds__(256) void prep_pow()
{
    int gw = blockIdx.x * 8 + (threadIdx.x >> 5);   // 0..1023 = layer*256+h
    int n  = threadIdx.x & 31;
    float4 p = d_SSMP[gw * 32 + n];
    float lr = p.x, li = p.y, tcr = p.z, tci = p.w;
    float curr = 1.f, curi = 0.f;                    // lambda^j
    float* W1p = d_W1 + (size_t)gw * (Tc * 64);
    float* B3p = d_B3 + (size_t)gw * (192 * Tc);
    float* Kvp = d_Kv + gw * Tc;
    for (int j = 0; j <= 128; j++) {
        if (j < 128) {
            float kr = tcr * curr - tci * curi;
            float ki = tcr * curi + tci * curr;
            W1p[(127 - j) * 64 + n]      = to_tf32(kr);
            W1p[(127 - j) * 64 + 32 + n] = to_tf32(ki);
            float s = kr;
#pragma unroll
            for (int o = 16; o; o >>= 1) s += __shfl_xor_sync(0xffffffffu, s, o);
            if (n == 0) Kvp[j] = s;
        }
        if (j >= 1) {
            int i = j - 1;
            B3p[(128 + n) * Tc + i] = to_tf32(curr);    //  Re(lambda^{i+1})
            B3p[(160 + n) * Tc + i] = to_tf32(-curi);   // -Im(lambda^{i+1})
        }
        if (j == 128) d_lamT[gw * 32 + n] = make_float2(curr, curi);
        float nr2 = curr * lr - curi * li;
        curi = curr * li + curi * lr;
        curr = nr2;
    }
}

// Toeplitz rows of B3 (with D folded into the diagonal)
__global__ __launch_bounds__(128) void prep_tk(const float* __restrict__ Dp)
{
    int gw = blockIdx.x;          // layer*256+h
    int i  = threadIdx.x;         // 0..127
    __shared__ float Ks[Tc];
    Ks[i] = d_Kv[gw * Tc + i];
    __syncthreads();
    float Dh = Dp[gw];
    float* B3p = d_B3 + (size_t)gw * (192 * Tc);
    for (int j = 0; j < 128; j++) {
        float v = 0.f;
        if (i >= j) v = Ks[i - j] + (i == j ? Dh : 0.f);
        B3p[j * Tc + i] = to_tf32(v);
    }
}

__global__ __launch_bounds__(256) void prep_w2(
    const float* __restrict__ W_glu, const float* __restrict__ b_glu)
{
    int idx = blockIdx.x * 256 + threadIdx.x;      // NL*H*256 = 262144
    int i = idx >> 16;
    int rem = idx & 65535;
    int h = rem >> 8;
    int j = rem & 255;
    const float* src = W_glu + ((size_t)i * Hn + h) * (2 * Hn);
    float* dst = d_W2 + ((size_t)i * Hn + h) * (2 * Hn);
    dst[2 * j]     = to_tf32(src[j]);
    dst[2 * j + 1] = to_tf32(src[j + Hn]);
    if (idx < NLn * Hn) {
        int i2 = idx >> 8, j2 = idx & 255;
        d_b2[i2 * 512 + 2 * j2]     = b_glu[i2 * 512 + j2];
        d_b2[i2 * 512 + 2 * j2 + 1] = b_glu[i2 * 512 + Hn + j2];
    }
}

// ---------------- input projection ----------------
__global__ __launch_bounds__(256) void in_proj(
    const float* __restrict__ x, const float* __restrict__ W, const float* __restrict__ bias)
{
    __shared__ float xs[32][DINn];
    int tid = threadIdx.x;
    int r0 = blockIdx.x * 32;
    for (int t = tid; t < 32 * DINn; t += 256)
        xs[t / DINn][t % DINn] = x[(size_t)r0 * DINn + t];
    float w[DINn];
#pragma unroll
    for (int k = 0; k < DINn; k++) w[k] = W[k * Hn + tid];
    float bv = bias[tid];
    __syncthreads();
#pragma unroll 4
    for (int r = 0; r < 32; r++) {
        float a = bv;
#pragma unroll
        for (int k = 0; k < DINn; k++) a = fmaf(xs[r][k], w[k], a);
        d_X[((size_t)(r0 + r)) * Hn + tid] = a;
    }
}

// ---------------- LayerNorm + transpose to (B, H, Lpad); writes fp32 + tf32 copies ---
__global__ __launch_bounds__(256) void ln_t_kernel(
    int layer, const float* __restrict__ ln_g, const float* __restrict__ ln_b)
{
    __shared__ float tile[32][257];
    __shared__ float mu[32], sc[32];
    int b  = blockIdx.y;
    int l0 = blockIdx.x * 32;
    int tid = threadIdx.x, lane = tid & 31, wid = tid >> 5;
    const float* Xb = d_X + (size_t)b * Ln * Hn;
#pragma unroll
    for (int r = 0; r < 32; r++) {
        int l = l0 + r;
        tile[r][tid] = (l < Ln) ? Xb[(size_t)l * Hn + tid] : 0.f;
    }
    __syncthreads();
#pragma unroll
    for (int rr = 0; rr < 4; rr++) {
        int r = wid * 4 + rr;
        float s = 0.f, q = 0.f;
#pragma unroll
        for (int k = 0; k < 8; k++) {
            float v = tile[r][k * 32 + lane];
            s += v; q += v * v;
        }
#pragma unroll
        for (int o = 16; o; o >>= 1) {
            s += __shfl_xor_sync(0xffffffffu, s, o);
            q += __shfl_xor_sync(0xffffffffu, q, o);
        }
        if (lane == 0) {
            float m = s * (1.f / 256.f);
            float v = q * (1.f / 256.f) - m * m;
            mu[r] = m;
            sc[r] = rsqrtf(v + 1e-5f);
        }
    }
    __syncthreads();
    const float* g  = ln_g + layer * Hn;
    const float* bb = ln_b + layer * Hn;
    float* Zb  = d_Zt  + (size_t)b * Hn * LP;
    float* Zrb = d_Ztr + (size_t)b * Hn * LP;
    int l = l0 + lane;
    if (l < Ln) {
        float m = mu[lane], s = sc[lane];
#pragma unroll
        for (int hi = 0; hi < 32; hi++) {
            int h = wid * 32 + hi;
            float zv = (tile[lane][h] - m) * s * g[h] + bb[h];
            Zb [(size_t)h * LP + l] = zv;
            Zrb[(size_t)h * LP + l] = to_tf32(zv);
        }
    }
}

// ---------------- stage 1: q = u_chunk @ W1  (M=640, N=64, K=128), 3-stage pipe -----
__global__ __launch_bounds__(256) void st1_kernel(int layer)
{
    extern __shared__ float sm[];
    float* As = sm;                   // 3 bufs [128][36]
    float* Bs = sm + 3 * 128 * 36;    // 3 bufs [32][72]
    int h  = blockIdx.y;
    int m0 = blockIdx.x * 128;
    int tid = threadIdx.x, lane = tid & 31, wid = tid >> 5;
    int wm = wid & 3, wn = wid >> 2;        // warp tile 32(M) x 32(N)
    int tg = lane & 3, gp = lane >> 2;

    int mA = tid >> 3;
    int sA = (tid & 7) * 4;
    const float* baseU[4];
#pragma unroll
    for (int i = 0; i < 4; i++) {
        int gm = m0 + mA + i * 32;
        int bb = gm / Cc, cc = gm % Cc;
        baseU[i] = d_Ztr + ((size_t)(bb * Hn + h)) * LP + cc * Tc + sA;
    }
    int kB = tid >> 4;                 // 0..15 (+16)
    int sB = (tid & 15) * 4;
    const float* W1p = d_W1 + (size_t)(layer * Hn + h) * (Tc * 64);

    float acc[2][4][4] = {};

    auto fill = [&](int s) {
        float* dA = As + (s % 3) * (128 * 36);
#pragma unroll
        for (int i = 0; i < 4; i++)
            cp16(dA + (mA + i * 32) * 36 + sA, baseU[i] + s * 32);
        float* dB = Bs + (s % 3) * (32 * 72);
        const float* sBb = W1p + (size_t)(s * 32) * 64 + sB;
#pragma unroll
        for (int i = 0; i < 2; i++)
            cp16(dB + (kB + i * 16) * 72 + sB, sBb + (size_t)(kB + i * 16) * 64);
    };

    fill(0); cp_commit();
    fill(1); cp_commit();
#pragma unroll
    for (int s = 0; s < 4; s++) {
        if (s < 3) cp_wait<1>(); else cp_wait<0>();
        __syncthreads();
        if (s + 2 < 4) { fill(s + 2); cp_commit(); }
        const float* a  = As + (s % 3) * (128 * 36);
        const float* bp = Bs + (s % 3) * (32 * 72);
#pragma unroll
        for (int ks = 0; ks < 32; ks += 8) {
            uint32_t af[2][4], bf[4][2];
#pragma unroll
            for (int mi = 0; mi < 2; mi++) {
                int mb = wm * 32 + mi * 16;
                af[mi][0] = __float_as_uint(a[(mb + gp    ) * 36 + ks + tg    ]);
                af[mi][1] = __float_as_uint(a[(mb + gp + 8) * 36 + ks + tg    ]);
                af[mi][2] = __float_as_uint(a[(mb + gp    ) * 36 + ks + tg + 4]);
                af[mi][3] = __float_as_uint(a[(mb + gp + 8) * 36 + ks + tg + 4]);
            }
#pragma unroll
            for (int ni = 0; ni < 4; ni++) {
                int nb = wn * 32 + ni * 8;
                bf[ni][0] = __float_as_uint(bp[(ks + tg    ) * 72 + nb + gp]);
                bf[ni][1] = __float_as_uint(bp[(ks + tg + 4) * 72 + nb + gp]);
            }
#pragma unroll
            for (int mi = 0; mi < 2; mi++)
#pragma unroll
                for (int ni = 0; ni < 4; ni++)
                    mma_tf32(acc[mi][ni], af[mi], bf[ni]);
        }
    }

#pragma unroll
    for (int mi = 0; mi < 2; mi++) {
#pragma unroll
        for (int ni = 0; ni < 4; ni++) {
            int n = wn * 32 + ni * 8 + tg * 2;
#pragma unroll
            for (int hf = 0; hf < 2; hf++) {
                int grow = m0 + wm * 32 + mi * 16 + gp + hf * 8;
                int b2 = grow / Cc, c2 = grow % Cc;
                size_t addr = ((size_t)(b2 * Hn + h) * Cc + c2) * 64 + n;
                d_Q[addr]     = acc[mi][ni][hf * 2];
                d_Q[addr + 1] = acc[mi][ni][hf * 2 + 1];
            }
        }
    }
}

// ---------------- stage 2: serial state pass over chunks -> Pt2[h][m][n] (tf32) -----
__global__ __launch_bounds__(256) void st2_kernel(int layer)
{
    int t = blockIdx.x * 256 + threadIdx.x;   // 131072
    int n = t & 31;
    int bh = t >> 5;                          // b*256+h
    int h = bh & 255, b = bh >> 8;
    float2 lt = d_lamT[(layer * Hn + h) * 32 + n];
    const float* qp = d_Q + (size_t)bh * (Cc * 64);
    float* pp = d_Pt2 + ((size_t)h * Mrows + b * Cc) * 64;
    float pr = 0.f, pi = 0.f;
    for (int c = 0; c < Cc; c++) {
        pp[c * 64 + n]      = to_tf32(pr);
        pp[c * 64 + 32 + n] = to_tf32(pi);
        float qr = qp[c * 64 + n], qi = qp[c * 64 + 32 + n];
        float prn = fmaf(lt.x, pr, fmaf(-lt.y, pi, qr));
        pi        = fmaf(lt.y, pr, fmaf( lt.x, pi, qi));
        pr = prn;
    }
}

// ---------------- stage 3: y = [u | p] @ [T_K+D | V], gelu -> Gt (tf32), 3-stage ----
__global__ __launch_bounds__(256) void st3_kernel(int layer)
{
    extern __shared__ float sm[];
    float* As = sm;                   // 3 bufs [128][36]
    float* Bs = sm + 3 * 128 * 36;    // 3 bufs [32][136]
    int h  = blockIdx.y;
    int m0 = blockIdx.x * 128;
    int tid = threadIdx.x, lane = tid & 31, wid = tid >> 5;
    int wm = wid & 3, wn = wid >> 2;          // warp tile 32(M) x 64(N)
    int tg = lane & 3, gp = lane >> 2;

    int mA = tid >> 3;
    int sA = (tid & 7) * 4;
    const float* baseU[4];
    const float* baseP[4];
#pragma unroll
    for (int i = 0; i < 4; i++) {
        int gm = m0 + mA + i * 32;
        int bb = gm / Cc, cc = gm % Cc;
        baseU[i] = d_Ztr + ((size_t)(bb * Hn + h)) * LP + cc * Tc + sA;
        baseP[i] = d_Pt2 + ((size_t)h * Mrows + gm) * 64 + sA;
    }
    int kB = tid >> 5;                 // 0..7 (+8,16,24)
    int sB = (tid & 31) * 4;
    const float* B3p = d_B3 + (size_t)(layer * Hn + h) * (192 * Tc) + sB;

    float acc[2][8][4] = {};

    auto fill = [&](int s) {
        int kt = s * 32;
        float* dA = As + (s % 3) * (128 * 36);
#pragma unroll
        for (int i = 0; i < 4; i++) {
            const float* src = (kt < 128) ? (baseU[i] + kt) : (baseP[i] + (kt - 128));
            cp16(dA + (mA + i * 32) * 36 + sA, src);
        }
        float* dB = Bs + (s % 3) * (32 * 136);
        const float* sBb = B3p + (size_t)kt * Tc;
#pragma unroll
        for (int i = 0; i < 4; i++)
            cp16(dB + (kB + i * 8) * 136 + sB, sBb + (size_t)(kB + i * 8) * Tc);
    };

    fill(0); cp_commit();
    fill(1); cp_commit();
#pragma unroll
    for (int s = 0; s < 6; s++) {
        if (s < 5) cp_wait<1>(); else cp_wait<0>();
        __syncthreads();
        if (s + 2 < 6) { fill(s + 2); cp_commit(); }
        const float* a  = As + (s % 3) * (128 * 36);
        const float* bp = Bs + (s % 3) * (32 * 136);
#pragma unroll
        for (int ks = 0; ks < 32; ks += 8) {
            uint32_t af[2][4], bf[8][2];
#pragma unroll
            for (int mi = 0; mi < 2; mi++) {
                int mb = wm * 32 + mi * 16;
                af[mi][0] = __float_as_uint(a[(mb + gp    ) * 36 + ks + tg    ]);
                af[mi][1] = __float_as_uint(a[(mb + gp + 8) * 36 + ks + tg    ]);
                af[mi][2] = __float_as_uint(a[(mb + gp    ) * 36 + ks + tg + 4]);
                af[mi][3] = __float_as_uint(a[(mb + gp + 8) * 36 + ks + tg + 4]);
            }
#pragma unroll
            for (int ni = 0; ni < 8; ni++) {
                int nb = wn * 64 + ni * 8;
                bf[ni][0] = __float_as_uint(bp[(ks + tg    ) * 136 + nb + gp]);
                bf[ni][1] = __float_as_uint(bp[(ks + tg + 4) * 136 + nb + gp]);
            }
#pragma unroll
            for (int mi = 0; mi < 2; mi++)
#pragma unroll
                for (int ni = 0; ni < 8; ni++)
                    mma_tf32(acc[mi][ni], af[mi], bf[ni]);
        }
    }

#pragma unroll
    for (int mi = 0; mi < 2; mi++) {
#pragma unroll
        for (int ni = 0; ni < 8; ni++) {
            int i = wn * 64 + ni * 8 + tg * 2;
#pragma unroll
            for (int hf = 0; hf < 2; hf++) {
                int grow = m0 + wm * 32 + mi * 16 + gp + hf * 8;
                int b2 = grow / Cc, c2 = grow % Cc;
                float* Grow = d_Gt + ((size_t)(b2 * Hn + h)) * LP + c2 * Tc;
                Grow[i]     = to_tf32(gelu_fast(acc[mi][ni][hf * 2]));
                Grow[i + 1] = to_tf32(gelu_fast(acc[mi][ni][hf * 2 + 1]));
            }
        }
    }
}

// ---------------- GLU GEMM (3-stage tf32 pipe) + bias + GLU + residual --------------
// grid: (n-tiles=4 fastest for A-tile L2 reuse, m-tiles=40, b=16)
__global__ __launch_bounds__(256) void glu_gemm_kernel(int layer)
{
    extern __shared__ float sm[];
    float* As = sm;                  // 3 bufs [32][136]
    float* Bs = sm + 3 * 32 * 136;   // 3 bufs [32][136]
    const int n0 = blockIdx.x * 128;
    const int m0 = blockIdx.y * 128;
    const int b  = blockIdx.z;
    int tid = threadIdx.x, lane = tid & 31, wid = tid >> 5;
    int wm = wid & 3, wn = wid >> 2;
    int tg = lane & 3, gp = lane >> 2;

    int kr = tid >> 5;                // 0..7 (+8,16,24)
    int sf = (tid & 31) * 4;
    const float* Ag = d_Gt + (size_t)b * (Hn * LP) + m0 + sf;
    const float* Bg = d_W2 + (size_t)layer * (Hn * 512) + n0 + sf;

    float acc[2][8][4] = {};

    auto fill = [&](int s) {
        float* dA = As + (s % 3) * (32 * 136);
        float* dB = Bs + (s % 3) * (32 * 136);
        const float* sAa = Ag + (size_t)(s * 32 + kr) * LP;
        const float* sBb = Bg + (size_t)(s * 32 + kr) * 512;
#pragma unroll
        for (int i = 0; i < 4; i++) {
            cp16(dA + (kr + i * 8) * 136 + sf, sAa + (size_t)i * 8 * LP);
            cp16(dB + (kr + i * 8) * 136 + sf, sBb + (size_t)i * 8 * 512);
        }
    };

    fill(0); cp_commit();
    fill(1); cp_commit();
#pragma unroll
    for (int s = 0; s < 8; s++) {
        if (s < 7) cp_wait<1>(); else cp_wait<0>();
        __syncthreads();
        if (s + 2 < 8) { fill(s + 2); cp_commit(); }
        const float* a  = As + (s % 3) * (32 * 136);
        const float* bp = Bs + (s % 3) * (32 * 136);
#pragma unroll
        for (int ks = 0; ks < 32; ks += 8) {
            uint32_t af[2][4], bf[8][2];
#pragma unroll
            for (int mi = 0; mi < 2; mi++) {
                int mb = wm * 32 + mi * 16;
                af[mi][0] = __float_as_uint(a[(ks + tg    ) * 136 + mb + gp    ]);
                af[mi][1] = __float_as_uint(a[(ks + tg    ) * 136 + mb + gp + 8]);
                af[mi][2] = __float_as_uint(a[(ks + tg + 4) * 136 + mb + gp    ]);
                af[mi][3] = __float_as_uint(a[(ks + tg + 4) * 136 + mb + gp + 8]);
            }
#pragma unroll
            for (int ni = 0; ni < 8; ni++) {
                int nb = wn * 64 + ni * 8;
                bf[ni][0] = __float_as_uint(bp[(ks + tg    ) * 136 + nb + gp]);
                bf[ni][1] = __float_as_uint(bp[(ks + tg + 4) * 136 + nb + gp]);
            }
#pragma unroll
            for (int mi = 0; mi < 2; mi++)
#pragma unroll
                for (int ni = 0; ni < 8; ni++)
                    mma_tf32(acc[mi][ni], af[mi], bf[ni]);
        }
    }

    const float* Zb  = d_Zt + (size_t)b * (Hn * LP);
    const float* b2p = d_b2 + layer * 512;
#pragma unroll
    for (int mi = 0; mi < 2; mi++) {
        int mrow = wm * 32 + mi * 16 + gp;
#pragma unroll
        for (int ni = 0; ni < 8; ni++) {
            int nc = wn * 64 + ni * 8 + tg * 2;
            int j  = (n0 + nc) >> 1;
            float ba = b2p[n0 + nc], bg = b2p[n0 + nc + 1];
#pragma unroll
            for (int hf = 0; hf < 2; hf++) {
                int l = m0 + mrow + hf * 8;
                if (l < Ln) {
                    float av   = acc[mi][ni][hf * 2 + 0] + ba;
                    float gate = acc[mi][ni][hf * 2 + 1] + bg;
                    float o = av * (1.f / (1.f + __expf(-gate)));
                    o += Zb[(size_t)j * LP + l];
                    d_X[((size_t)b * Ln + l) * Hn + j] = o;
                }
            }
        }
    }
}

// ---------------- final LayerNorm -> d_out ----------------
__global__ __launch_bounds__(256) void final_ln(
    const float* __restrict__ g, const float* __restrict__ bb, float* __restrict__ out)
{
    int lane = threadIdx.x & 31, wid = threadIdx.x >> 5;
    size_t row = (size_t)blockIdx.x * 8 + wid;
    const float* xr = d_X + row * Hn;
    float v[8], s = 0.f, q = 0.f;
#pragma unroll
    for (int k = 0; k < 8; k++) {
        v[k] = xr[k * 32 + lane];
        s += v[k]; q += v[k] * v[k];
    }
#pragma unroll
    for (int o = 16; o; o >>= 1) {
        s += __shfl_xor_sync(0xffffffffu, s, o);
        q += __shfl_xor_sync(0xffffffffu, q, o);
    }
    float m  = s * (1.f / 256.f);
    float sc = rsqrtf(q * (1.f / 256.f) - m * m + 1e-5f);
#pragma unroll
    for (int k = 0; k < 8; k++) {
        int h = k * 32 + lane;
        out[row * Hn + h] = (v[k] - m) * sc * g[h] + bb[h];
    }
}

// ---------------- launch ----------------
extern "C" void kernel_launch(void* const* d_in, const int* in_sizes, int n_in,
                              void* d_out, int out_size)
{
    const float* x       = (const float*)d_in[0];
    const float* W_in    = (const float*)d_in[1];
    const float* b_in    = (const float*)d_in[2];
    const float* ln_g    = (const float*)d_in[3];
    const float* ln_b    = (const float*)d_in[4];
    const float* log_dt  = (const float*)d_in[5];
    const float* logA_re = (const float*)d_in[6];
    const float* A_im    = (const float*)d_in[7];
    const float* Cp      = (const float*)d_in[8];
    const float* Dp      = (const float*)d_in[9];
    const float* W_glu   = (const float*)d_in[10];
    const float* b_glu   = (const float*)d_in[11];
    const float* fn_g    = (const float*)d_in[12];
    const float* fn_b    = (const float*)d_in[13];
    float* out = (float*)d_out;

    const int smem_st1 = (3 * 128 * 36 + 3 * 32 * 72) * 4;    // 82944
    const int smem_st3 = (3 * 128 * 36 + 3 * 32 * 136) * 4;   // 107520
    const int smem_glu = (3 * 32 * 136 * 2) * 4;              // 104448
    cudaFuncSetAttribute(st1_kernel, cudaFuncAttributeMaxDynamicSharedMemorySize, smem_st1);
    cudaFuncSetAttribute(st3_kernel, cudaFuncAttributeMaxDynamicSharedMemorySize, smem_st3);
    cudaFuncSetAttribute(glu_gemm_kernel, cudaFuncAttributeMaxDynamicSharedMemorySize, smem_glu);

    prep_ssm<<<128, 256>>>(log_dt, logA_re, A_im, Cp);
    prep_pow<<<128, 256>>>();
    prep_tk<<<NLn * Hn, 128>>>(Dp);
    prep_w2<<<1024, 256>>>(W_glu, b_glu);
    in_proj<<<2500, 256>>>(x, W_in, b_in);

    for (int i = 0; i < NLn; i++) {
        dim3 gln((Ln + 31) / 32, Bn);
        ln_t_kernel<<<gln, 256>>>(i, ln_g, ln_b);
        st1_kernel<<<dim3(Mrows / 128, Hn), 256, smem_st1>>>(i);
        st2_kernel<<<512, 256>>>(i);
        st3_kernel<<<dim3(Mrows / 128, Hn), 256, smem_st3>>>(i);
        dim3 gg(4, LP / 128, Bn);   // n fastest -> A-tile L2 reuse
        glu_gemm_kernel<<<gg, 256, smem_glu>>>(i);
    }
    final_ln<<<(Bn * Ln) / 8, 256>>>(fn_g, fn_b, out);
}

// round 5
// speedup vs baseline: 2.4351x; 1.0945x over previous
#include <cuda_runtime.h>
#include <cstdint>
#include <math.h>

#define Bn   16
#define Ln   5000
#define Hn   256
#define Nn   32
#define NLn  4
#define DINn 12
#define Tc   128          // chunk length
#define Cc   40           // chunks (padded length 5120)
#define LP   5120         // padded L
#define Mrows (Bn * Cc)   // 640 chunk-rows

// ---------------- scratch (device globals; zero-initialized) ----------------
__device__ __align__(16) float  d_X  [(size_t)Bn * Ln * Hn];   // activations (B, L, H)
__device__ __align__(16) float  d_Zl [(size_t)Bn * Ln * Hn];   // LN output fp32 (B, L, H) residual
__device__ __align__(16) float  d_Ztr[(size_t)Bn * Hn * LP];   // LN output tf32, (B,H,Lpad), pad=0
__device__ __align__(16) float  d_Gt [(size_t)Bn * Hn * LP];   // tf32(gelu(y)), (B, H, Lpad)
__device__ __align__(16) float4 d_SSMP[NLn * Hn * Nn];         // (lam_re, lam_im, 2Ct_re, 2Ct_im)
__device__ __align__(16) float  d_W2[NLn * Hn * 2 * Hn];       // tf32(W_glu) interleaved halves
__device__ __align__(16) float  d_b2[NLn * 2 * Hn];
__device__ __align__(16) float  d_Q  [(size_t)Bn * Hn * Cc * 64];   // chunk state contributions
__device__ __align__(16) float  d_Pt2[(size_t)Hn * Mrows * 64];     // tf32 chunk-start states [h][m][n]
__device__ __align__(16) float  d_W1[(size_t)NLn * Hn * Tc * 64];   // stage-1 B (tf32)
__device__ __align__(16) float  d_B3[(size_t)NLn * Hn * 192 * Tc];  // stage-3 B (tf32)
__device__ __align__(16) float  d_Kv[NLn * Hn * Tc];
__device__ __align__(16) float2 d_lamT[NLn * Hn * Nn];              // lambda^128

// ---------------- helpers ----------------
__device__ __forceinline__ float to_tf32(float x) {
    uint32_t u;
    asm("cvt.rna.tf32.f32 %0, %1;" : "=r"(u) : "f"(x));
    return __uint_as_float(u);
}

__device__ __forceinline__ void cp16(float* dst, const float* src) {
    uint32_t d = (uint32_t)__cvta_generic_to_shared(dst);
    asm volatile("cp.async.cg.shared.global [%0], [%1], 16;\n" :: "r"(d), "l"(src));
}
__device__ __forceinline__ void cp_commit() {
    asm volatile("cp.async.commit_group;\n");
}
template <int N>
__device__ __forceinline__ void cp_wait() {
    asm volatile("cp.async.wait_group %0;\n" :: "n"(N));
}

__device__ __forceinline__ void mma_tf32(float* d, const uint32_t* a, const uint32_t* b) {
    asm volatile(
        "mma.sync.aligned.m16n8k8.row.col.f32.tf32.tf32.f32 "
        "{%0,%1,%2,%3}, {%4,%5,%6,%7}, {%8,%9}, {%0,%1,%2,%3};\n"
        : "+f"(d[0]), "+f"(d[1]), "+f"(d[2]), "+f"(d[3])
        : "r"(a[0]), "r"(a[1]), "r"(a[2]), "r"(a[3]), "r"(b[0]), "r"(b[1]));
}

// exact tanh-gelu rewritten as x*sigmoid(2t); __expf error ~1e-6 (invisible under tf32)
__device__ __forceinline__ float gelu_fast(float x) {
    float t2 = 1.5957691216057308f * fmaf(0.044715f, x * x * x, x);
    return x * (1.f / (1.f + __expf(-t2)));
}

// ---------------- param prep ----------------
__global__ __launch_bounds__(256) void prep_ssm(
    const float* __restrict__ log_dt, const float* __restrict__ logA_re,
    const float* __restrict__ A_im,   const float* __restrict__ Cp)
{
    int idx = blockIdx.x * 256 + threadIdx.x;      // NL*H*N = 32768
    int i = idx / (Hn * Nn);
    int h = (idx / Nn) % Hn;
    float dt  = expf(log_dt[i * Hn + h]);
    float aRe = -expf(logA_re[idx]);
    float aIm = A_im[idx];
    float er  = expf(aRe * dt);
    float ang = aIm * dt;
    float lr = er * cosf(ang), li = er * sinf(ang);
    float nr = lr - 1.f, ni = li;
    float inv = 1.f / (aRe * aRe + aIm * aIm);
    float qr = (nr * aRe + ni * aIm) * inv;
    float qi = (ni * aRe - nr * aIm) * inv;
    float cr = Cp[2 * idx], ci = Cp[2 * idx + 1];
    float Ctr = cr * qr - ci * qi;
    float Cti = cr * qi + ci * qr;
    d_SSMP[idx] = make_float4(lr, li, 2.f * Ctr, 2.f * Cti);
}

// powers of lambda -> W1 (stage1 B), V rows of B3, lamT, K vector
__global__ __launch_bounds__(256) void prep_pow()
{
    int gw = blockIdx.x * 8 + (threadIdx.x >> 5);   // 0..1023 = layer*256+h
    int n  = threadIdx.x & 31;
    float4 p = d_SSMP[gw * 32 + n];
    float lr = p.x, li = p.y, tcr = p.z, tci = p.w;
    float curr = 1.f, curi = 0.f;                    // lambda^j
    float* W1p = d_W1 + (size_t)gw * (Tc * 64);
    float* B3p = d_B3 + (size_t)gw * (192 * Tc);
    float* Kvp = d_Kv + gw * Tc;
    for (int j = 0; j <= 128; j++) {
        if (j < 128) {
            float kr = tcr * curr - tci * curi;
            float ki = tcr * curi + tci * curr;
            W1p[(127 - j) * 64 + n]      = to_tf32(kr);
            W1p[(127 - j) * 64 + 32 + n] = to_tf32(ki);
            float s = kr;
#pragma unroll
            for (int o = 16; o; o >>= 1) s += __shfl_xor_sync(0xffffffffu, s, o);
            if (n == 0) Kvp[j] = s;
        }
        if (j >= 1) {
            int i = j - 1;
            B3p[(128 + n) * Tc + i] = to_tf32(curr);    //  Re(lambda^{i+1})
            B3p[(160 + n) * Tc + i] = to_tf32(-curi);   // -Im(lambda^{i+1})
        }
        if (j == 128) d_lamT[gw * 32 + n] = make_float2(curr, curi);
        float nr2 = curr * lr - curi * li;
        curi = curr * li + curi * lr;
        curr = nr2;
    }
}

// Toeplitz rows of B3 (with D folded into the diagonal)
__global__ __launch_bounds__(128) void prep_tk(const float* __restrict__ Dp)
{
    int gw = blockIdx.x;          // layer*256+h
    int i  = threadIdx.x;         // 0..127
    __shared__ float Ks[Tc];
    Ks[i] = d_Kv[gw * Tc + i];
    __syncthreads();
    float Dh = Dp[gw];
    float* B3p = d_B3 + (size_t)gw * (192 * Tc);
    for (int j = 0; j < 128; j++) {
        float v = 0.f;
        if (i >= j) v = Ks[i - j] + (i == j ? Dh : 0.f);
        B3p[j * Tc + i] = to_tf32(v);
    }
}

__global__ __launch_bounds__(256) void prep_w2(
    const float* __restrict__ W_glu, const float* __restrict__ b_glu)
{
    int idx = blockIdx.x * 256 + threadIdx.x;      // NL*H*256 = 262144
    int i = idx >> 16;
    int rem = idx & 65535;
    int h = rem >> 8;
    int j = rem & 255;
    const float* src = W_glu + ((size_t)i * Hn + h) * (2 * Hn);
    float* dst = d_W2 + ((size_t)i * Hn + h) * (2 * Hn);
    dst[2 * j]     = to_tf32(src[j]);
    dst[2 * j + 1] = to_tf32(src[j + Hn]);
    if (idx < NLn * Hn) {
        int i2 = idx >> 8, j2 = idx & 255;
        d_b2[i2 * 512 + 2 * j2]     = b_glu[i2 * 512 + j2];
        d_b2[i2 * 512 + 2 * j2 + 1] = b_glu[i2 * 512 + Hn + j2];
    }
}

// ---------------- input projection ----------------
__global__ __launch_bounds__(256) void in_proj(
    const float* __restrict__ x, const float* __restrict__ W, const float* __restrict__ bias)
{
    __shared__ float xs[32][DINn];
    int tid = threadIdx.x;
    int r0 = blockIdx.x * 32;
    for (int t = tid; t < 32 * DINn; t += 256)
        xs[t / DINn][t % DINn] = x[(size_t)r0 * DINn + t];
    float w[DINn];
#pragma unroll
    for (int k = 0; k < DINn; k++) w[k] = W[k * Hn + tid];
    float bv = bias[tid];
    __syncthreads();
#pragma unroll 4
    for (int r = 0; r < 32; r++) {
        float a = bv;
#pragma unroll
        for (int k = 0; k < DINn; k++) a = fmaf(xs[r][k], w[k], a);
        d_X[((size_t)(r0 + r)) * Hn + tid] = a;
    }
}

// ---- LayerNorm: writes Ztr (tf32, transposed, for GEMMs) + Zl (fp32, straight, residual)
__global__ __launch_bounds__(256) void ln_t_kernel(
    int layer, const float* __restrict__ ln_g, const float* __restrict__ ln_b)
{
    __shared__ float tile[32][257];
    __shared__ float mu[32], sc[32];
    int b  = blockIdx.y;
    int l0 = blockIdx.x * 32;
    int tid = threadIdx.x, lane = tid & 31, wid = tid >> 5;
    const float* Xb = d_X + (size_t)b * Ln * Hn;
#pragma unroll
    for (int r = 0; r < 32; r++) {
        int l = l0 + r;
        tile[r][tid] = (l < Ln) ? Xb[(size_t)l * Hn + tid] : 0.f;
    }
    __syncthreads();
#pragma unroll
    for (int rr = 0; rr < 4; rr++) {
        int r = wid * 4 + rr;
        float s = 0.f, q = 0.f;
#pragma unroll
        for (int k = 0; k < 8; k++) {
            float v = tile[r][k * 32 + lane];
            s += v; q += v * v;
        }
#pragma unroll
        for (int o = 16; o; o >>= 1) {
            s += __shfl_xor_sync(0xffffffffu, s, o);
            q += __shfl_xor_sync(0xffffffffu, q, o);
        }
        if (lane == 0) {
            float m = s * (1.f / 256.f);
            float v = q * (1.f / 256.f) - m * m;
            mu[r] = m;
            sc[r] = rsqrtf(v + 1e-5f);
        }
    }
    __syncthreads();
    const float* g  = ln_g + layer * Hn;
    const float* bb = ln_b + layer * Hn;
    float gh = g[tid], bh = bb[tid];
    // straight (B,L,H) fp32 residual write, coalesced in h=tid
    float* Zlb = d_Zl + (size_t)b * Ln * Hn;
#pragma unroll 4
    for (int r = 0; r < 32; r++) {
        int l = l0 + r;
        if (l < Ln)
            Zlb[(size_t)l * Hn + tid] = (tile[r][tid] - mu[r]) * sc[r] * gh + bh;
    }
    // transposed (B,H,LP) tf32 write for GEMM A-operands
    float* Zrb = d_Ztr + (size_t)b * Hn * LP;
    int l = l0 + lane;
    if (l < Ln) {
        float m = mu[lane], s = sc[lane];
#pragma unroll
        for (int hi = 0; hi < 32; hi++) {
            int h = wid * 32 + hi;
            float zv = (tile[lane][h] - m) * s * g[h] + bb[h];
            Zrb[(size_t)h * LP + l] = to_tf32(zv);
        }
    }
}

// ---------------- stage 1: q = u_chunk @ W1  (M=640, N=64, K=128), 3-stage pipe -----
__global__ __launch_bounds__(256) void st1_kernel(int layer)
{
    extern __shared__ float sm[];
    float* As = sm;                   // 3 bufs [128][36]
    float* Bs = sm + 3 * 128 * 36;    // 3 bufs [32][72]
    int h  = blockIdx.y;
    int m0 = blockIdx.x * 128;
    int tid = threadIdx.x, lane = tid & 31, wid = tid >> 5;
    int wm = wid & 3, wn = wid >> 2;        // warp tile 32(M) x 32(N)
    int tg = lane & 3, gp = lane >> 2;

    int mA = tid >> 3;
    int sA = (tid & 7) * 4;
    const float* baseU[4];
#pragma unroll
    for (int i = 0; i < 4; i++) {
        int gm = m0 + mA + i * 32;
        int bb = gm / Cc, cc = gm % Cc;
        baseU[i] = d_Ztr + ((size_t)(bb * Hn + h)) * LP + cc * Tc + sA;
    }
    int kB = tid >> 4;                 // 0..15 (+16)
    int sB = (tid & 15) * 4;
    const float* W1p = d_W1 + (size_t)(layer * Hn + h) * (Tc * 64);

    float acc[2][4][4] = {};

    auto fill = [&](int s) {
        float* dA = As + (s % 3) * (128 * 36);
#pragma unroll
        for (int i = 0; i < 4; i++)
            cp16(dA + (mA + i * 32) * 36 + sA, baseU[i] + s * 32);
        float* dB = Bs + (s % 3) * (32 * 72);
        const float* sBb = W1p + (size_t)(s * 32) * 64 + sB;
#pragma unroll
        for (int i = 0; i < 2; i++)
            cp16(dB + (kB + i * 16) * 72 + sB, sBb + (size_t)(kB + i * 16) * 64);
    };

    fill(0); cp_commit();
    fill(1); cp_commit();
#pragma unroll
    for (int s = 0; s < 4; s++) {
        if (s < 3) cp_wait<1>(); else cp_wait<0>();
        __syncthreads();
        if (s + 2 < 4) { fill(s + 2); cp_commit(); }
        const float* a  = As + (s % 3) * (128 * 36);
        const float* bp = Bs + (s % 3) * (32 * 72);
#pragma unroll
        for (int ks = 0; ks < 32; ks += 8) {
            uint32_t af[2][4], bf[4][2];
#pragma unroll
            for (int mi = 0; mi < 2; mi++) {
                int mb = wm * 32 + mi * 16;
                af[mi][0] = __float_as_uint(a[(mb + gp    ) * 36 + ks + tg    ]);
                af[mi][1] = __float_as_uint(a[(mb + gp + 8) * 36 + ks + tg    ]);
                af[mi][2] = __float_as_uint(a[(mb + gp    ) * 36 + ks + tg + 4]);
                af[mi][3] = __float_as_uint(a[(mb + gp + 8) * 36 + ks + tg + 4]);
            }
#pragma unroll
            for (int ni = 0; ni < 4; ni++) {
                int nb = wn * 32 + ni * 8;
                bf[ni][0] = __float_as_uint(bp[(ks + tg    ) * 72 + nb + gp]);
                bf[ni][1] = __float_as_uint(bp[(ks + tg + 4) * 72 + nb + gp]);
            }
#pragma unroll
            for (int mi = 0; mi < 2; mi++)
#pragma unroll
                for (int ni = 0; ni < 4; ni++)
                    mma_tf32(acc[mi][ni], af[mi], bf[ni]);
        }
    }

#pragma unroll
    for (int mi = 0; mi < 2; mi++) {
#pragma unroll
        for (int ni = 0; ni < 4; ni++) {
            int n = wn * 32 + ni * 8 + tg * 2;
#pragma unroll
            for (int hf = 0; hf < 2; hf++) {
                int grow = m0 + wm * 32 + mi * 16 + gp + hf * 8;
                int b2 = grow / Cc, c2 = grow % Cc;
                size_t addr = ((size_t)(b2 * Hn + h) * Cc + c2) * 64 + n;
                d_Q[addr]     = acc[mi][ni][hf * 2];
                d_Q[addr + 1] = acc[mi][ni][hf * 2 + 1];
            }
        }
    }
}

// ---------------- stage 2: serial state pass over chunks -> Pt2[h][m][n] (tf32) -----
__global__ __launch_bounds__(256) void st2_kernel(int layer)
{
    int t = blockIdx.x * 256 + threadIdx.x;   // 131072
    int n = t & 31;
    int bh = t >> 5;                          // b*256+h
    int h = bh & 255, b = bh >> 8;
    float2 lt = d_lamT[(layer * Hn + h) * 32 + n];
    const float* qp = d_Q + (size_t)bh * (Cc * 64);
    float* pp = d_Pt2 + ((size_t)h * Mrows + b * Cc) * 64;
    float pr = 0.f, pi = 0.f;
    for (int c = 0; c < Cc; c++) {
        pp[c * 64 + n]      = to_tf32(pr);
        pp[c * 64 + 32 + n] = to_tf32(pi);
        float qr = qp[c * 64 + n], qi = qp[c * 64 + 32 + n];
        float prn = fmaf(lt.x, pr, fmaf(-lt.y, pi, qr));
        pi        = fmaf(lt.y, pr, fmaf( lt.x, pi, qi));
        pr = prn;
    }
}

// ---------------- stage 3: y = [u | p] @ [T_K+D | V], gelu -> Gt (tf32), 3-stage ----
__global__ __launch_bounds__(256) void st3_kernel(int layer)
{
    extern __shared__ float sm[];
    float* As = sm;                   // 3 bufs [128][36]
    float* Bs = sm + 3 * 128 * 36;    // 3 bufs [32][136]
    int h  = blockIdx.y;
    int m0 = blockIdx.x * 128;
    int tid = threadIdx.x, lane = tid & 31, wid = tid >> 5;
    int wm = wid & 3, wn = wid >> 2;          // warp tile 32(M) x 64(N)
    int tg = lane & 3, gp = lane >> 2;

    int mA = tid >> 3;
    int sA = (tid & 7) * 4;
    const float* baseU[4];
    const float* baseP[4];
#pragma unroll
    for (int i = 0; i < 4; i++) {
        int gm = m0 + mA + i * 32;
        int bb = gm / Cc, cc = gm % Cc;
        baseU[i] = d_Ztr + ((size_t)(bb * Hn + h)) * LP + cc * Tc + sA;
        baseP[i] = d_Pt2 + ((size_t)h * Mrows + gm) * 64 + sA;
    }
    int kB = tid >> 5;                 // 0..7 (+8,16,24)
    int sB = (tid & 31) * 4;
    const float* B3p = d_B3 + (size_t)(layer * Hn + h) * (192 * Tc) + sB;

    float acc[2][8][4] = {};

    auto fill = [&](int s) {
        int kt = s * 32;
        float* dA = As + (s % 3) * (128 * 36);
#pragma unroll
        for (int i = 0; i < 4; i++) {
            const float* src = (kt < 128) ? (baseU[i] + kt) : (baseP[i] + (kt - 128));
            cp16(dA + (mA + i * 32) * 36 + sA, src);
        }
        float* dB = Bs + (s % 3) * (32 * 136);
        const float* sBb = B3p + (size_t)kt * Tc;
#pragma unroll
        for (int i = 0; i < 4; i++)
            cp16(dB + (kB + i * 8) * 136 + sB, sBb + (size_t)(kB + i * 8) * Tc);
    };

    fill(0); cp_commit();
    fill(1); cp_commit();
#pragma unroll
    for (int s = 0; s < 6; s++) {
        if (s < 5) cp_wait<1>(); else cp_wait<0>();
        __syncthreads();
        if (s + 2 < 6) { fill(s + 2); cp_commit(); }
        const float* a  = As + (s % 3) * (128 * 36);
        const float* bp = Bs + (s % 3) * (32 * 136);
#pragma unroll
        for (int ks = 0; ks < 32; ks += 8) {
            uint32_t af[2][4], bf[8][2];
#pragma unroll
            for (int mi = 0; mi < 2; mi++) {
                int mb = wm * 32 + mi * 16;
                af[mi][0] = __float_as_uint(a[(mb + gp    ) * 36 + ks + tg    ]);
                af[mi][1] = __float_as_uint(a[(mb + gp + 8) * 36 + ks + tg    ]);
                af[mi][2] = __float_as_uint(a[(mb + gp    ) * 36 + ks + tg + 4]);
                af[mi][3] = __float_as_uint(a[(mb + gp + 8) * 36 + ks + tg + 4]);
            }
#pragma unroll
            for (int ni = 0; ni < 8; ni++) {
                int nb = wn * 64 + ni * 8;
                bf[ni][0] = __float_as_uint(bp[(ks + tg    ) * 136 + nb + gp]);
                bf[ni][1] = __float_as_uint(bp[(ks + tg + 4) * 136 + nb + gp]);
            }
#pragma unroll
            for (int mi = 0; mi < 2; mi++)
#pragma unroll
                for (int ni = 0; ni < 8; ni++)
                    mma_tf32(acc[mi][ni], af[mi], bf[ni]);
        }
    }

    // stage gelu output through smem, then coalesced float4 stores to Gt
    __syncthreads();
    float* stg = sm;                      // [128][132]
#pragma unroll
    for (int mi = 0; mi < 2; mi++) {
#pragma unroll
        for (int ni = 0; ni < 8; ni++) {
            int i = wn * 64 + ni * 8 + tg * 2;
#pragma unroll
            for (int hf = 0; hf < 2; hf++) {
                int ml = wm * 32 + mi * 16 + gp + hf * 8;
                stg[ml * 132 + i]     = to_tf32(gelu_fast(acc[mi][ni][hf * 2]));
                stg[ml * 132 + i + 1] = to_tf32(gelu_fast(acc[mi][ni][hf * 2 + 1]));
            }
        }
    }
    __syncthreads();
#pragma unroll
    for (int it = 0; it < 16; it++) {
        int idx = tid + it * 256;         // 4096 float4 tasks
        int row = idx >> 5, f4 = (idx & 31) * 4;
        int grow = m0 + row;
        int b2 = grow / Cc, c2 = grow % Cc;
        float4 v = *(const float4*)(stg + row * 132 + f4);
        *(float4*)(d_Gt + ((size_t)(b2 * Hn + h)) * LP + c2 * Tc + f4) = v;
    }
}

// ---------------- GLU GEMM (3-stage tf32 pipe) + bias + GLU + residual --------------
// grid: (n-tiles=4 fastest for A-tile L2 reuse, m-tiles=40, b=16)
__global__ __launch_bounds__(256) void glu_gemm_kernel(int layer)
{
    extern __shared__ float sm[];
    float* As = sm;                  // 3 bufs [32][136]
    float* Bs = sm + 3 * 32 * 136;   // 3 bufs [32][136]
    const int n0 = blockIdx.x * 128;
    const int m0 = blockIdx.y * 128;
    const int b  = blockIdx.z;
    int tid = threadIdx.x, lane = tid & 31, wid = tid >> 5;
    int wm = wid & 3, wn = wid >> 2;
    int tg = lane & 3, gp = lane >> 2;

    int kr = tid >> 5;                // 0..7 (+8,16,24)
    int sf = (tid & 31) * 4;
    const float* Ag = d_Gt + (size_t)b * (Hn * LP) + m0 + sf;
    const float* Bg = d_W2 + (size_t)layer * (Hn * 512) + n0 + sf;

    float acc[2][8][4] = {};

    auto fill = [&](int s) {
        float* dA = As + (s % 3) * (32 * 136);
        float* dB = Bs + (s % 3) * (32 * 136);
        const float* sAa = Ag + (size_t)(s * 32 + kr) * LP;
        const float* sBb = Bg + (size_t)(s * 32 + kr) * 512;
#pragma unroll
        for (int i = 0; i < 4; i++) {
            cp16(dA + (kr + i * 8) * 136 + sf, sAa + (size_t)i * 8 * LP);
            cp16(dB + (kr + i * 8) * 136 + sf, sBb + (size_t)i * 8 * 512);
        }
    };

    fill(0); cp_commit();
    fill(1); cp_commit();
#pragma unroll
    for (int s = 0; s < 8; s++) {
        if (s < 7) cp_wait<1>(); else cp_wait<0>();
        __syncthreads();
        if (s + 2 < 8) { fill(s + 2); cp_commit(); }
        const float* a  = As + (s % 3) * (32 * 136);
        const float* bp = Bs + (s % 3) * (32 * 136);
#pragma unroll
        for (int ks = 0; ks < 32; ks += 8) {
            uint32_t af[2][4], bf[8][2];
#pragma unroll
            for (int mi = 0; mi < 2; mi++) {
                int mb = wm * 32 + mi * 16;
                af[mi][0] = __float_as_uint(a[(ks + tg    ) * 136 + mb + gp    ]);
                af[mi][1] = __float_as_uint(a[(ks + tg    ) * 136 + mb + gp + 8]);
                af[mi][2] = __float_as_uint(a[(ks + tg + 4) * 136 + mb + gp    ]);
                af[mi][3] = __float_as_uint(a[(ks + tg + 4) * 136 + mb + gp + 8]);
            }
#pragma unroll
            for (int ni = 0; ni < 8; ni++) {
                int nb = wn * 64 + ni * 8;
                bf[ni][0] = __float_as_uint(bp[(ks + tg    ) * 136 + nb + gp]);
                bf[ni][1] = __float_as_uint(bp[(ks + tg + 4) * 136 + nb + gp]);
            }
#pragma unroll
            for (int mi = 0; mi < 2; mi++)
#pragma unroll
                for (int ni = 0; ni < 8; ni++)
                    mma_tf32(acc[mi][ni], af[mi], bf[ni]);
        }
    }

    // bias + GLU into smem stage, then coalesced residual-add + store
    const float* b2p = d_b2 + layer * 512;
    __syncthreads();
    float* so = sm;                        // [128][68]
#pragma unroll
    for (int mi = 0; mi < 2; mi++) {
#pragma unroll
        for (int ni = 0; ni < 8; ni++) {
            int nc = wn * 64 + ni * 8 + tg * 2;
            int jl = nc >> 1;                       // local channel 0..63
            float ba = b2p[n0 + nc], bg = b2p[n0 + nc + 1];
#pragma unroll
            for (int hf = 0; hf < 2; hf++) {
                int ml = wm * 32 + mi * 16 + gp + hf * 8;
                float av   = acc[mi][ni][hf * 2 + 0] + ba;
                float gate = acc[mi][ni][hf * 2 + 1] + bg;
                so[ml * 68 + jl] = av * (1.f / (1.f + __expf(-gate)));
            }
        }
    }
    __syncthreads();
    const int j0 = n0 >> 1;
    const float* Zlb = d_Zl + (size_t)b * Ln * Hn + j0;
    float* Xb = d_X + (size_t)b * Ln * Hn + j0;
#pragma unroll
    for (int it = 0; it < 8; it++) {
        int idx = tid + it * 256;          // 2048 float4 tasks
        int row = idx >> 4, f4 = (idx & 15) * 4;
        int l = m0 + row;
        if (l < Ln) {
            float4 o = *(const float4*)(so + row * 68 + f4);
            float4 z = *(const float4*)(Zlb + (size_t)l * Hn + f4);
            o.x += z.x; o.y += z.y; o.z += z.z; o.w += z.w;
            *(float4*)(Xb + (size_t)l * Hn + f4) = o;
        }
    }
}

// ---------------- final LayerNorm -> d_out ----------------
__global__ __launch_bounds__(256) void final_ln(
    const float* __restrict__ g, const float* __restrict__ bb, float* __restrict__ out)
{
    int lane = threadIdx.x & 31, wid = threadIdx.x >> 5;
    size_t row = (size_t)blockIdx.x * 8 + wid;
    const float* xr = d_X + row * Hn;
    float v[8], s = 0.f, q = 0.f;
#pragma unroll
    for (int k = 0; k < 8; k++) {
        v[k] = xr[k * 32 + lane];
        s += v[k]; q += v[k] * v[k];
    }
#pragma unroll
    for (int o = 16; o; o >>= 1) {
        s += __shfl_xor_sync(0xffffffffu, s, o);
        q += __shfl_xor_sync(0xffffffffu, q, o);
    }
    float m  = s * (1.f / 256.f);
    float sc = rsqrtf(q * (1.f / 256.f) - m * m + 1e-5f);
#pragma unroll
    for (int k = 0; k < 8; k++) {
        int h = k * 32 + lane;
        out[row * Hn + h] = (v[k] - m) * sc * g[h] + bb[h];
    }
}

// ---------------- launch ----------------
extern "C" void kernel_launch(void* const* d_in, const int* in_sizes, int n_in,
                              void* d_out, int out_size)
{
    const float* x       = (const float*)d_in[0];
    const float* W_in    = (const float*)d_in[1];
    const float* b_in    = (const float*)d_in[2];
    const float* ln_g    = (const float*)d_in[3];
    const float* ln_b    = (const float*)d_in[4];
    const float* log_dt  = (const float*)d_in[5];
    const float* logA_re = (const float*)d_in[6];
    const float* A_im    = (const float*)d_in[7];
    const float* Cp      = (const float*)d_in[8];
    const float* Dp      = (const float*)d_in[9];
    const float* W_glu   = (const float*)d_in[10];
    const float* b_glu   = (const float*)d_in[11];
    const float* fn_g    = (const float*)d_in[12];
    const float* fn_b    = (const float*)d_in[13];
    float* out = (float*)d_out;

    const int smem_st1 = (3 * 128 * 36 + 3 * 32 * 72) * 4;    // 82944
    const int smem_st3 = (3 * 128 * 36 + 3 * 32 * 136) * 4;   // 107520 (>= 128*132*4 stage)
    const int smem_glu = (3 * 32 * 136 * 2) * 4;              // 104448 (>= 128*68*4 stage)
    cudaFuncSetAttribute(st1_kernel, cudaFuncAttributeMaxDynamicSharedMemorySize, smem_st1);
    cudaFuncSetAttribute(st3_kernel, cudaFuncAttributeMaxDynamicSharedMemorySize, smem_st3);
    cudaFuncSetAttribute(glu_gemm_kernel, cudaFuncAttributeMaxDynamicSharedMemorySize, smem_glu);

    prep_ssm<<<128, 256>>>(log_dt, logA_re, A_im, Cp);
    prep_pow<<<128, 256>>>();
    prep_tk<<<NLn * Hn, 128>>>(Dp);
    prep_w2<<<1024, 256>>>(W_glu, b_glu);
    in_proj<<<2500, 256>>>(x, W_in, b_in);

    for (int i = 0; i < NLn; i++) {
        dim3 gln((Ln + 31) / 32, Bn);
        ln_t_kernel<<<gln, 256>>>(i, ln_g, ln_b);
        st1_kernel<<<dim3(Mrows / 128, Hn), 256, smem_st1>>>(i);
        st2_kernel<<<512, 256>>>(i);
        st3_kernel<<<dim3(Mrows / 128, Hn), 256, smem_st3>>>(i);
        dim3 gg(4, LP / 128, Bn);   // n fastest -> A-tile L2 reuse
        glu_gemm_kernel<<<gg, 256, smem_glu>>>(i);
    }
    final_ln<<<(Bn * Ln) / 8, 256>>>(fn_g, fn_b, out);
}